// round 1
// baseline (speedup 1.0000x reference)
#include <cuda_runtime.h>

#define Bn   4
#define Cn   256
#define Hf   64
#define Wf   64
#define HW   (Hf*Wf)
#define COMPn 64
#define S2n  4
#define K2n  25
#define Mn   100
#define OH   128
#define OW   128

// Scratch (device globals — no allocation allowed)
__device__ float g_act[Bn*COMPn*HW];     // 4 MB : compressed+BN+SiLU activations [b][o][pix]
__device__ float g_mask[Bn*HW*Mn];       // 6.5 MB: softmaxed masks, per-pixel contiguous [pix][s*25+k]

// ---------------------------------------------------------------------------
// Kernel 1: 1x1 compression conv (GEMM 64x256 @ 256x4096) + BatchNorm + SiLU
// grid (B*16, 2), block 256. Each block: 256 pixels x 32 output channels.
// Weights staged in smem, consumed as float4 (1 LDS.128 per 4 FMA).
// ---------------------------------------------------------------------------
__global__ __launch_bounds__(256) void k1_comp_bn_silu(
    const float* __restrict__ x, const float* __restrict__ w_comp,
    const float* __restrict__ gamma, const float* __restrict__ beta,
    const float* __restrict__ mean, const float* __restrict__ var)
{
    __shared__ float sw[32*256];
    const int tid  = threadIdx.x;
    const int b    = blockIdx.x >> 4;
    const int pix  = ((blockIdx.x & 15) << 8) + tid;
    const int oBase = blockIdx.y << 5;

    #pragma unroll
    for (int i = 0; i < 32; i++)
        sw[i*256 + tid] = w_comp[(oBase + i)*256 + tid];
    __syncthreads();

    float acc[32];
    #pragma unroll
    for (int o = 0; o < 32; o++) acc[o] = 0.f;

    const float* xb = x + (size_t)b*Cn*HW + pix;
    const float4* sw4 = reinterpret_cast<const float4*>(sw);

    #pragma unroll 1
    for (int c4 = 0; c4 < 64; c4++) {
        float x0 = xb[(c4*4+0)*HW];
        float x1 = xb[(c4*4+1)*HW];
        float x2 = xb[(c4*4+2)*HW];
        float x3 = xb[(c4*4+3)*HW];
        #pragma unroll
        for (int o = 0; o < 32; o++) {
            float4 w = sw4[o*64 + c4];
            acc[o] += x0*w.x + x1*w.y + x2*w.z + x3*w.w;
        }
    }

    #pragma unroll
    for (int o = 0; o < 32; o++) {
        int og = oBase + o;
        float inv = gamma[og] * rsqrtf(var[og] + 1e-5f);
        float v = (acc[o] - mean[og]) * inv + beta[og];
        float sg = 1.f / (1.f + __expf(-v));
        g_act[((size_t)b*COMPn + og)*HW + pix] = v * sg;
    }
}

// ---------------------------------------------------------------------------
// Kernel 2: 3x3 encoder conv (64 -> 100 channels, pad 1) + softmax over the 25
// k-taps per (sub-pixel s, pixel). Thread = (pixel-pair, s). m = k*4 + s, so
// each thread owns exactly the 25 values it must softmax — no cross-thread
// reduction. Weights + act patch staged in smem in c-chunks of 8; each weight
// LDS amortized over 2 pixels (18 FMA per 9 weight LDS).
// grid (4, 8, B): 16x8 pixel tiles. block 256.
// ---------------------------------------------------------------------------
#define TW 16
#define TH 8
#define CCH 8

__global__ __launch_bounds__(256) void k2_conv_softmax(
    const float* __restrict__ w_enc)
{
    __shared__ float s_act[CCH*10*18];   // (TH+2) x (TW+2) patch per channel
    __shared__ float s_w[CCH*Mn*9];      // [cl][m][9]

    const int tid   = threadIdx.x;
    const int q     = tid & 3;            // sub-pixel s
    const int pp    = tid >> 2;           // pixel-pair 0..63
    const int trow  = pp >> 3;            // 0..7
    const int tcol0 = (pp & 7) << 1;      // 0,2,...,14
    const int b     = blockIdx.z;
    const int col0  = blockIdx.x * TW;
    const int row0  = blockIdx.y * TH;

    float acc[K2n][2];
    #pragma unroll
    for (int t = 0; t < K2n; t++) { acc[t][0] = 0.f; acc[t][1] = 0.f; }

    const float* actb = g_act + (size_t)b*COMPn*HW;

    for (int cc = 0; cc < COMPn; cc += CCH) {
        // stage activation patch (zero-padded)
        for (int idx = tid; idx < CCH*10*18; idx += 256) {
            int cl = idx / 180;
            int r  = idx - cl*180;
            int ly = r / 18, lx = r - ly*18;
            int gy = row0 - 1 + ly, gx = col0 - 1 + lx;
            float v = 0.f;
            if ((unsigned)gy < Hf && (unsigned)gx < Wf)
                v = actb[(cc+cl)*HW + gy*Wf + gx];
            s_act[idx] = v;
        }
        // stage weights: s_w[cl][m][j] = w_enc[m][cc+cl][j]
        for (int idx = tid; idx < CCH*Mn*9; idx += 256) {
            int cl = idx / 900;
            int r  = idx - cl*900;
            int m  = r / 9, j = r - m*9;
            s_w[idx] = w_enc[m*(COMPn*9) + (cc+cl)*9 + j];
        }
        __syncthreads();

        #pragma unroll 1
        for (int cl = 0; cl < CCH; cl++) {
            float a[3][4];
            const float* pa = s_act + cl*180 + trow*18 + tcol0;
            #pragma unroll
            for (int ky = 0; ky < 3; ky++)
                #pragma unroll
                for (int kx = 0; kx < 4; kx++)
                    a[ky][kx] = pa[ky*18 + kx];

            const float* pw = s_w + cl*900 + q*9;  // m = t*4 + q -> stride 36 floats over t
            #pragma unroll
            for (int t = 0; t < K2n; t++) {
                const float* w9 = pw + t*36;
                #pragma unroll
                for (int ky = 0; ky < 3; ky++)
                    #pragma unroll
                    for (int kx = 0; kx < 3; kx++) {
                        float w = w9[ky*3 + kx];
                        acc[t][0] += a[ky][kx]   * w;
                        acc[t][1] += a[ky][kx+1] * w;
                    }
            }
        }
        __syncthreads();
    }

    // softmax over the 25 k-taps, in place, then store per-pixel contiguous
    const int gi = row0 + trow;
    const int gj = col0 + tcol0;
    #pragma unroll
    for (int p = 0; p < 2; p++) {
        float mx = acc[0][p];
        #pragma unroll
        for (int t = 1; t < K2n; t++) mx = fmaxf(mx, acc[t][p]);
        float sum = 0.f;
        #pragma unroll
        for (int t = 0; t < K2n; t++) { acc[t][p] = __expf(acc[t][p] - mx); sum += acc[t][p]; }
        float r = 1.f / sum;
        float* out = g_mask + ((size_t)(b*HW + gi*Wf + gj + p))*Mn + q*K2n;
        #pragma unroll
        for (int t = 0; t < K2n; t++) out[t] = acc[t][p] * r;
    }
}

// ---------------------------------------------------------------------------
// Kernel 3: content-aware reassembly + pixel-shuffle store.
// Thread = (pixel in 8x8 tile, c_sub in 4). The pixel's 100 mask values live
// in REGISTERS (loaded once as float4), so the inner loop per channel is
// 25 LDS (5x5 x-window from smem) + 100 FMA. Output written as float2 pairs
// (the two s1 sub-columns are adjacent) for coalescing.
// grid (8, 8, B). block 256, 1 block/SM (reg-heavy by design).
// ---------------------------------------------------------------------------
__global__ __launch_bounds__(256, 1) void k3_reassemble(
    const float* __restrict__ x, float* __restrict__ out)
{
    __shared__ float s_x[4*12*12];  // 4 channels x (8+4)^2 patch

    const int tid  = threadIdx.x;
    const int px   = tid & 63;
    const int cs   = tid >> 6;       // 0..3
    const int trow = px >> 3, tcol = px & 7;
    const int b    = blockIdx.z;
    const int col0 = blockIdx.x * 8, row0 = blockIdx.y * 8;
    const int gi = row0 + trow, gj = col0 + tcol;
    const int pix = gi*Wf + gj;

    // Pixel's softmaxed mask -> 100 registers (layout [s*25 + k])
    float mreg[100];
    const float4* mp = reinterpret_cast<const float4*>(g_mask + (size_t)(b*HW + pix)*Mn);
    #pragma unroll
    for (int i = 0; i < 25; i++) {
        float4 v = mp[i];
        mreg[4*i] = v.x; mreg[4*i+1] = v.y; mreg[4*i+2] = v.z; mreg[4*i+3] = v.w;
    }

    const float* xb   = x   + (size_t)b*Cn*HW;
    float*       outb = out + (size_t)b*Cn*OH*OW;

    #pragma unroll 1
    for (int co = 0; co < 64; co++) {
        __syncthreads();  // protect previous iteration's reads
        for (int idx = tid; idx < 576; idx += 256) {
            int cl = idx / 144;
            int r  = idx - cl*144;
            int ly = r / 12, lx = r - ly*12;
            int gy = row0 - 2 + ly, gx = col0 - 2 + lx;
            float v = 0.f;
            if ((unsigned)gy < Hf && (unsigned)gx < Wf)
                v = xb[(co*4 + cl)*HW + gy*Wf + gx];
            s_x[idx] = v;
        }
        __syncthreads();

        float a0 = 0.f, a1 = 0.f, a2 = 0.f, a3 = 0.f;
        const float* p = s_x + cs*144 + trow*12 + tcol;
        #pragma unroll
        for (int k = 0; k < 25; k++) {
            const int dy = k / 5, dx = k - dy*5;
            float xv = p[dy*12 + dx];
            a0 += mreg[k]      * xv;   // s=(0,0)
            a1 += mreg[25 + k] * xv;   // s=(0,1)
            a2 += mreg[50 + k] * xv;   // s=(1,0)
            a3 += mreg[75 + k] * xv;   // s=(1,1)
        }

        const int cg = co*4 + cs;
        float* op = outb + (size_t)cg*OH*OW;
        *reinterpret_cast<float2*>(op + (2*gi    )*OW + 2*gj) = make_float2(a0, a1);
        *reinterpret_cast<float2*>(op + (2*gi + 1)*OW + 2*gj) = make_float2(a2, a3);
    }
}

// ---------------------------------------------------------------------------
extern "C" void kernel_launch(void* const* d_in, const int* in_sizes, int n_in,
                              void* d_out, int out_size)
{
    const float* x      = (const float*)d_in[0];
    const float* w_comp = (const float*)d_in[1];
    const float* gamma  = (const float*)d_in[2];
    const float* beta   = (const float*)d_in[3];
    const float* mean   = (const float*)d_in[4];
    const float* var    = (const float*)d_in[5];
    const float* w_enc  = (const float*)d_in[6];
    float* out = (float*)d_out;

    k1_comp_bn_silu<<<dim3(Bn*16, 2), 256>>>(x, w_comp, gamma, beta, mean, var);
    k2_conv_softmax<<<dim3(4, 8, Bn), 256>>>(w_enc);
    k3_reassemble<<<dim3(8, 8, Bn), 256>>>(x, out);
}

// round 2
// speedup vs baseline: 1.1203x; 1.1203x over previous
#include <cuda_runtime.h>

#define Bn   4
#define Cn   256
#define Hf   64
#define Wf   64
#define HW   (Hf*Wf)
#define COMPn 64
#define K2n  25
#define Mn   100
#define OH   128
#define OW   128
#define EPSc 1e-5f

typedef unsigned long long u64t;

// packed fp32x2 helpers (FFMA2 — only reachable via PTX)
#define FMA2(d, a, b, c) asm("fma.rn.f32x2 %0, %1, %2, %3;" : "=l"(d) : "l"(a), "l"(b), "l"(c))

__device__ __forceinline__ u64t dup2(float v) {
    u64t r; asm("mov.b64 %0, {%1, %1};" : "=l"(r) : "f"(v)); return r;
}
__device__ __forceinline__ float2 unpk(u64t v) {
    float lo, hi; asm("mov.b64 {%0, %1}, %2;" : "=f"(lo), "=f"(hi) : "l"(v));
    return make_float2(lo, hi);
}
__device__ __forceinline__ u64t pack2(float a, float b) {
    u64t r; asm("mov.b64 %0, {%1, %2};" : "=l"(r) : "f"(a), "f"(b)); return r;
}

// Scratch (device globals — no allocation allowed)
__device__ float g_act[Bn*COMPn*HW];   // [b][o][pix]
__device__ float g_mask[Bn*HW*Mn];     // [b*HW+pix][m], m = t*4 + s  (m-order!)

// ---------------------------------------------------------------------------
// K1: 1x1 compression (GEMM) + BN + SiLU, packed over 2 adjacent pixels.
// x loaded as LDG.64 (naturally packed pixel pair). Weights duplicated in
// smem so LDS.128 yields two (w,w) pairs — zero pack cost.
// grid (Bn*16, 4) = 256 blocks, 128 threads. Each block: 256 px x 16 outputs.
// ---------------------------------------------------------------------------
__global__ __launch_bounds__(128) void k1_comp_bn_silu(
    const float* __restrict__ x, const float* __restrict__ w_comp,
    const float* __restrict__ gamma, const float* __restrict__ beta,
    const float* __restrict__ mean, const float* __restrict__ var)
{
    __shared__ __align__(16) float sw[16*256*2];   // dup pairs, 32KB

    const int tid     = threadIdx.x;
    const int b       = blockIdx.x >> 4;
    const int pixBase = (blockIdx.x & 15) << 8;
    const int oBase   = blockIdx.y << 4;

    for (int i = tid; i < 16*256; i += 128) {
        int o = i >> 8, c = i & 255;
        float w = w_comp[(oBase + o)*256 + c];
        sw[2*i] = w; sw[2*i+1] = w;
    }
    __syncthreads();

    const int pix0 = pixBase + 2*tid;
    const float* xb = x + (size_t)b*Cn*HW + pix0;

    u64t acc[16];
    #pragma unroll
    for (int o = 0; o < 16; o++) acc[o] = 0ULL;

    u64t nx0 = *(const u64t*)(xb + 0*HW);
    u64t nx1 = *(const u64t*)(xb + 1*HW);
    u64t nx2 = *(const u64t*)(xb + 2*HW);
    u64t nx3 = *(const u64t*)(xb + 3*HW);

    const ulonglong2* sw2 = reinterpret_cast<const ulonglong2*>(sw);

    #pragma unroll 1
    for (int c4 = 0; c4 < 64; c4++) {
        u64t x0 = nx0, x1 = nx1, x2 = nx2, x3 = nx3;
        if (c4 < 63) {
            const float* nb = xb + (c4+1)*4*HW;
            nx0 = *(const u64t*)(nb + 0*HW);
            nx1 = *(const u64t*)(nb + 1*HW);
            nx2 = *(const u64t*)(nb + 2*HW);
            nx3 = *(const u64t*)(nb + 3*HW);
        }
        #pragma unroll
        for (int o = 0; o < 16; o++) {
            ulonglong2 wA = sw2[o*128 + c4*2];       // (w0,w0),(w1,w1)
            ulonglong2 wB = sw2[o*128 + c4*2 + 1];   // (w2,w2),(w3,w3)
            FMA2(acc[o], wA.x, x0, acc[o]);
            FMA2(acc[o], wA.y, x1, acc[o]);
            FMA2(acc[o], wB.x, x2, acc[o]);
            FMA2(acc[o], wB.y, x3, acc[o]);
        }
    }

    #pragma unroll
    for (int o = 0; o < 16; o++) {
        int og = oBase + o;
        float inv = gamma[og] * rsqrtf(var[og] + EPSc);
        float mu = mean[og], bt = beta[og];
        float2 v = unpk(acc[o]);
        float v0 = (v.x - mu)*inv + bt;
        float v1 = (v.y - mu)*inv + bt;
        v0 = v0 / (1.f + __expf(-v0));
        v1 = v1 / (1.f + __expf(-v1));
        *reinterpret_cast<float2*>(&g_act[((size_t)b*COMPn + og)*HW + pix0]) = make_float2(v0, v1);
    }
}

// ---------------------------------------------------------------------------
// K2: 3x3 encoder conv (64->100) + softmax over 25 taps per (s, pixel).
// Thread = (2x2 pixel quad, s). Lanes = horizontal pixel pair (top & bottom
// accumulators). Weights duplicated in smem (LDS.128 => two dup-pairs).
// grid (8,8,Bn) = 256 blocks of 64 threads. acc: 50 packed regs.
// ---------------------------------------------------------------------------
#define CCH 4

__global__ __launch_bounds__(64) void k2_conv_softmax(const float* __restrict__ w_enc)
{
    __shared__ __align__(16) float s_w[CCH*100*10*2];  // [cl][m][10] float2-dup, 32KB
    __shared__ float s_act[CCH*100];                    // [cl][10][10]

    const int tid  = threadIdx.x;
    const int q    = tid & 3;
    const int quad = tid >> 2;         // 0..15
    const int qr   = quad >> 2, qc = quad & 3;
    const int b    = blockIdx.z;
    const int row0 = blockIdx.y * 8, col0 = blockIdx.x * 8;

    u64t accT[25], accB[25];
    #pragma unroll
    for (int t = 0; t < 25; t++) { accT[t] = 0ULL; accB[t] = 0ULL; }

    const float* actb = g_act + (size_t)b*COMPn*HW;

    for (int cc = 0; cc < COMPn; cc += CCH) {
        __syncthreads();   // previous chunk fully consumed
        for (int idx = tid; idx < CCH*100; idx += 64) {
            int cl = idx / 100, r = idx - cl*100;
            int ly = r / 10, lx = r - ly*10;
            int gy = row0 - 1 + ly, gx = col0 - 1 + lx;
            float v = 0.f;
            if ((unsigned)gy < Hf && (unsigned)gx < Wf)
                v = actb[(cc+cl)*HW + gy*Wf + gx];
            s_act[idx] = v;
        }
        for (int idx = tid; idx < CCH*900; idx += 64) {
            int cl = idx / 900, r = idx - cl*900;
            int m = r / 9, j = r - m*9;
            float w = w_enc[(m*COMPn + cc + cl)*9 + j];
            int o = ((cl*100 + m)*10 + j)*2;
            s_w[o] = w; s_w[o+1] = w;
        }
        __syncthreads();

        #pragma unroll 1
        for (int cl = 0; cl < CCH; cl++) {
            float a[4][4];
            const float* pa = s_act + cl*100 + (2*qr)*10 + 2*qc;
            #pragma unroll
            for (int r = 0; r < 4; r++)
                #pragma unroll
                for (int c = 0; c < 4; c++)
                    a[r][c] = pa[r*10 + c];

            u64t pk[4][3];
            #pragma unroll
            for (int r = 0; r < 4; r++)
                #pragma unroll
                for (int kx = 0; kx < 3; kx++)
                    pk[r][kx] = pack2(a[r][kx], a[r][kx+1]);

            const float* wp = s_w + ((cl*100 + q)*10)*2;   // m = t*4+q -> +t*80 floats
            #pragma unroll
            for (int t = 0; t < 25; t++) {
                const ulonglong2* w2 = reinterpret_cast<const ulonglong2*>(wp + t*80);
                ulonglong2 p0 = w2[0];   // j0=(0,0), j1=(0,1)
                ulonglong2 p1 = w2[1];   // j2=(0,2), j3=(1,0)
                ulonglong2 p2 = w2[2];   // j4=(1,1), j5=(1,2)
                ulonglong2 p3 = w2[3];   // j6=(2,0), j7=(2,1)
                u64t w8 = *reinterpret_cast<const u64t*>(wp + t*80 + 16);  // j8=(2,2)
                FMA2(accT[t], p0.x, pk[0][0], accT[t]); FMA2(accB[t], p0.x, pk[1][0], accB[t]);
                FMA2(accT[t], p0.y, pk[0][1], accT[t]); FMA2(accB[t], p0.y, pk[1][1], accB[t]);
                FMA2(accT[t], p1.x, pk[0][2], accT[t]); FMA2(accB[t], p1.x, pk[1][2], accB[t]);
                FMA2(accT[t], p1.y, pk[1][0], accT[t]); FMA2(accB[t], p1.y, pk[2][0], accB[t]);
                FMA2(accT[t], p2.x, pk[1][1], accT[t]); FMA2(accB[t], p2.x, pk[2][1], accB[t]);
                FMA2(accT[t], p2.y, pk[1][2], accT[t]); FMA2(accB[t], p2.y, pk[2][2], accB[t]);
                FMA2(accT[t], p3.x, pk[2][0], accT[t]); FMA2(accB[t], p3.x, pk[3][0], accB[t]);
                FMA2(accT[t], p3.y, pk[2][1], accT[t]); FMA2(accB[t], p3.y, pk[3][1], accB[t]);
                FMA2(accT[t], w8,   pk[2][2], accT[t]); FMA2(accB[t], w8,   pk[3][2], accB[t]);
            }
        }
    }

    // softmax over t for each of the 4 pixels, store in m-order (t*4+q)
    const int giT = row0 + 2*qr, gjL = col0 + 2*qc;
    #pragma unroll
    for (int half = 0; half < 2; half++) {
        float vx[25], vy[25];
        #pragma unroll
        for (int t = 0; t < 25; t++) {
            float2 u = unpk(half == 0 ? accT[t] : accB[t]);
            vx[t] = u.x; vy[t] = u.y;
        }
        int gi = giT + half;
        #pragma unroll
        for (int p = 0; p < 2; p++) {
            float* v = p ? vy : vx;
            float mx = v[0];
            #pragma unroll
            for (int t = 1; t < 25; t++) mx = fmaxf(mx, v[t]);
            float sum = 0.f;
            #pragma unroll
            for (int t = 0; t < 25; t++) { v[t] = __expf(v[t] - mx); sum += v[t]; }
            float r = 1.f / sum;
            float* outp = g_mask + ((size_t)(b*HW + gi*Wf + gjL + p))*Mn + q;
            #pragma unroll
            for (int t = 0; t < 25; t++) outp[t*4] = v[t] * r;
        }
    }
}

// ---------------------------------------------------------------------------
// K3: content-aware reassembly + pixel shuffle. Mask in m-order means one
// LDG.128 per tap gives packed (s0,s1)|(s2,s3) pairs -> 50 packed mask regs,
// zero pack cost. Lanes = (s-pair). Double-buffered x staging (1 bar/iter).
// grid (8,8,Bn*2) = 512 blocks, 128 threads (64 px x 2 channel slots).
// ---------------------------------------------------------------------------
__global__ __launch_bounds__(128) void k3_reassemble(
    const float* __restrict__ x, float* __restrict__ out)
{
    __shared__ __align__(16) float s_x[2][576];   // 4 ch x 12x12, double buffered

    const int tid  = threadIdx.x;
    const int px   = tid & 63;
    const int slot = tid >> 6;         // 0..1 (2 channels each)
    const int trow = px >> 3, tcol = px & 7;
    const int bz   = blockIdx.z;
    const int b    = bz >> 1;
    const int cbase = (bz & 1) * 128;
    const int col0 = blockIdx.x * 8, row0 = blockIdx.y * 8;
    const int gi = row0 + trow, gj = col0 + tcol;
    const int pix = gi*Wf + gj;

    // 100 mask values -> 50 packed regs
    u64t m01[25], m23[25];
    {
        const ulonglong2* mp = reinterpret_cast<const ulonglong2*>(
            g_mask + ((size_t)(b*HW + pix))*Mn);
        #pragma unroll
        for (int k = 0; k < 25; k++) {
            ulonglong2 mm = mp[k];
            m01[k] = mm.x; m23[k] = mm.y;
        }
    }

    const float* xb   = x   + (size_t)b*Cn*HW;
    float*       outb = out + (size_t)b*Cn*OH*OW;

    // stage helper: iteration 'it' covers channels cbase+it*4 .. +3
    float pre[5];
    {
        #pragma unroll
        for (int i = 0; i < 5; i++) {
            int idx = tid + i*128;
            float v = 0.f;
            if (idx < 576) {
                int cl = idx / 144, r = idx - cl*144;
                int ly = r / 12, lx = r - ly*12;
                int gy = row0 - 2 + ly, gx = col0 - 2 + lx;
                if ((unsigned)gy < Hf && (unsigned)gx < Wf)
                    v = xb[(cbase + cl)*HW + gy*Wf + gx];
            }
            pre[i] = v;
        }
        #pragma unroll
        for (int i = 0; i < 5; i++) { int idx = tid + i*128; if (idx < 576) s_x[0][idx] = pre[i]; }
        __syncthreads();
    }

    #pragma unroll 1
    for (int it = 0; it < 32; it++) {
        const int cur = it & 1;
        // prefetch next group's patch into registers (overlaps compute)
        if (it < 31) {
            #pragma unroll
            for (int i = 0; i < 5; i++) {
                int idx = tid + i*128;
                float v = 0.f;
                if (idx < 576) {
                    int cl = idx / 144, r = idx - cl*144;
                    int ly = r / 12, lx = r - ly*12;
                    int gy = row0 - 2 + ly, gx = col0 - 2 + lx;
                    if ((unsigned)gy < Hf && (unsigned)gx < Wf)
                        v = xb[(cbase + (it+1)*4 + cl)*HW + gy*Wf + gx];
                }
                pre[i] = v;
            }
        }

        const float* p0 = &s_x[cur][(slot*2)*144 + trow*12 + tcol];
        const float* p1 = p0 + 144;
        u64t a01_0 = 0ULL, a23_0 = 0ULL, a01_1 = 0ULL, a23_1 = 0ULL;
        #pragma unroll
        for (int k = 0; k < 25; k++) {
            const int dy = k / 5, dx = k - dy*5;
            const int off = dy*12 + dx;
            u64t xx0 = dup2(p0[off]);
            u64t xx1 = dup2(p1[off]);
            FMA2(a01_0, m01[k], xx0, a01_0);
            FMA2(a23_0, m23[k], xx0, a23_0);
            FMA2(a01_1, m01[k], xx1, a01_1);
            FMA2(a23_1, m23[k], xx1, a23_1);
        }

        const int c0 = cbase + it*4 + slot*2;
        float* op0 = outb + (size_t)c0*OH*OW;
        *reinterpret_cast<float2*>(op0 + (2*gi    )*OW + 2*gj) = unpk(a01_0);
        *reinterpret_cast<float2*>(op0 + (2*gi + 1)*OW + 2*gj) = unpk(a23_0);
        float* op1 = op0 + OH*OW;
        *reinterpret_cast<float2*>(op1 + (2*gi    )*OW + 2*gj) = unpk(a01_1);
        *reinterpret_cast<float2*>(op1 + (2*gi + 1)*OW + 2*gj) = unpk(a23_1);

        if (it < 31) {
            #pragma unroll
            for (int i = 0; i < 5; i++) { int idx = tid + i*128; if (idx < 576) s_x[cur ^ 1][idx] = pre[i]; }
        }
        __syncthreads();
    }
}

// ---------------------------------------------------------------------------
extern "C" void kernel_launch(void* const* d_in, const int* in_sizes, int n_in,
                              void* d_out, int out_size)
{
    const float* x      = (const float*)d_in[0];
    const float* w_comp = (const float*)d_in[1];
    const float* gamma  = (const float*)d_in[2];
    const float* beta   = (const float*)d_in[3];
    const float* mean   = (const float*)d_in[4];
    const float* var    = (const float*)d_in[5];
    const float* w_enc  = (const float*)d_in[6];
    float* out = (float*)d_out;

    k1_comp_bn_silu<<<dim3(Bn*16, 4), 128>>>(x, w_comp, gamma, beta, mean, var);
    k2_conv_softmax<<<dim3(8, 8, Bn), 64>>>(w_enc);
    k3_reassemble<<<dim3(8, 8, Bn*2), 128>>>(x, out);
}

// round 3
// speedup vs baseline: 1.3935x; 1.2438x over previous
#include <cuda_runtime.h>

#define Bn   4
#define Cn   256
#define Hf   64
#define Wf   64
#define HW   (Hf*Wf)
#define COMPn 64
#define Mn   100
#define OH   128
#define OW   128
#define EPSc 1e-5f
#define TPAD 28          // t dimension padded 25->28 for 16B alignment
#define MSTR 112         // g_mask per-pixel stride (4*TPAD), 448B, 16B-aligned

typedef unsigned long long u64t;

#define FMA2(d, a, b, c) asm("fma.rn.f32x2 %0, %1, %2, %3;" : "=l"(d) : "l"(a), "l"(b), "l"(c))

__device__ __forceinline__ u64t dup2(float v) {
    u64t r; asm("mov.b64 %0, {%1, %1};" : "=l"(r) : "f"(v)); return r;
}
__device__ __forceinline__ float2 unpk(u64t v) {
    float lo, hi; asm("mov.b64 {%0, %1}, %2;" : "=f"(lo), "=f"(hi) : "l"(v));
    return make_float2(lo, hi);
}

// Scratch
__device__ float g_act[Bn*COMPn*HW];          // [b][o][pix]
__device__ float g_mask[Bn*HW*MSTR];          // [b*HW+pix][t*4+s], padded stride

// ---------------------------------------------------------------------------
// K1: 1x1 compression + BN + SiLU. Packed over 2 adjacent pixels.
// 8 outputs/block -> 512 blocks of 128 threads (~14 warps/SM).
// ---------------------------------------------------------------------------
__global__ __launch_bounds__(128) void k1_comp_bn_silu(
    const float* __restrict__ x, const float* __restrict__ w_comp,
    const float* __restrict__ gamma, const float* __restrict__ beta,
    const float* __restrict__ mean, const float* __restrict__ var)
{
    __shared__ __align__(16) float sw[8*256*2];   // dup pairs, 16KB

    const int tid     = threadIdx.x;
    const int b       = blockIdx.x >> 4;
    const int pixBase = (blockIdx.x & 15) << 8;
    const int oBase   = blockIdx.y << 3;

    for (int i = tid; i < 8*256; i += 128) {
        int o = i >> 8, c = i & 255;
        float w = w_comp[(oBase + o)*256 + c];
        sw[2*i] = w; sw[2*i+1] = w;
    }
    __syncthreads();

    const int pix0 = pixBase + 2*tid;
    const float* xb = x + (size_t)b*Cn*HW + pix0;

    u64t acc[8];
    #pragma unroll
    for (int o = 0; o < 8; o++) acc[o] = 0ULL;

    u64t nx0 = *(const u64t*)(xb + 0*HW);
    u64t nx1 = *(const u64t*)(xb + 1*HW);
    u64t nx2 = *(const u64t*)(xb + 2*HW);
    u64t nx3 = *(const u64t*)(xb + 3*HW);

    const ulonglong2* sw2 = reinterpret_cast<const ulonglong2*>(sw);

    #pragma unroll 2
    for (int c4 = 0; c4 < 64; c4++) {
        u64t x0 = nx0, x1 = nx1, x2 = nx2, x3 = nx3;
        if (c4 < 63) {
            const float* nb = xb + (c4+1)*4*HW;
            nx0 = *(const u64t*)(nb + 0*HW);
            nx1 = *(const u64t*)(nb + 1*HW);
            nx2 = *(const u64t*)(nb + 2*HW);
            nx3 = *(const u64t*)(nb + 3*HW);
        }
        #pragma unroll
        for (int o = 0; o < 8; o++) {
            ulonglong2 wA = sw2[o*128 + c4*2];
            ulonglong2 wB = sw2[o*128 + c4*2 + 1];
            FMA2(acc[o], wA.x, x0, acc[o]);
            FMA2(acc[o], wA.y, x1, acc[o]);
            FMA2(acc[o], wB.x, x2, acc[o]);
            FMA2(acc[o], wB.y, x3, acc[o]);
        }
    }

    #pragma unroll
    for (int o = 0; o < 8; o++) {
        int og = oBase + o;
        float inv = gamma[og] * rsqrtf(var[og] + EPSc);
        float mu = mean[og], bt = beta[og];
        float2 v = unpk(acc[o]);
        float v0 = (v.x - mu)*inv + bt;
        float v1 = (v.y - mu)*inv + bt;
        v0 = v0 / (1.f + __expf(-v0));
        v1 = v1 / (1.f + __expf(-v1));
        *reinterpret_cast<float2*>(&g_act[((size_t)b*COMPn + og)*HW + pix0]) = make_float2(v0, v1);
    }
}

// ---------------------------------------------------------------------------
// K2: 3x3 encoder conv + softmax. Block = (one q, 16x16 px tile, one b).
// Weights for this q's 25 taps staged ONCE (63KB, t padded to 28).
// Acc packed over t-pairs: weights load naturally packed (LDS.128 -> 2 pairs),
// activations staged DUPLICATED (LDS.64 -> dup pair). 13 packed accs/thread.
// grid (4,4,16) = 256 blocks x 256 threads. Dynamic smem ~84KB.
// ---------------------------------------------------------------------------
__global__ __launch_bounds__(256) void k2_conv_softmax(const float* __restrict__ w_enc)
{
    extern __shared__ __align__(16) float smem[];
    float* s_w   = smem;                  // [c][j][TPAD]  64*9*28 = 16128 floats (63KB)
    float* s_act = smem + 64*9*TPAD;      // [8][18][18] duplicated: 8*324*2 floats (20.25KB)

    const int tid  = threadIdx.x;
    const int bz   = blockIdx.z;
    const int b    = bz >> 2;
    const int q    = bz & 3;
    const int row0 = blockIdx.y * 16, col0 = blockIdx.x * 16;
    const int trow = tid >> 4, tcol = tid & 15;

    // Stage weights once: s_w[(c*9+j)*TPAD + t] = w_enc[(t*4+q)][c][j]; coalesced reads.
    for (int i = tid; i < 576; i += 256) {
        s_w[i*TPAD + 25] = 0.f; s_w[i*TPAD + 26] = 0.f; s_w[i*TPAD + 27] = 0.f;
    }
    for (int idx = tid; idx < 25*576; idx += 256) {
        int t = idx / 576, cj = idx - t*576;
        s_w[cj*TPAD + t] = w_enc[(t*4 + q)*576 + cj];
    }

    u64t acc[13];
    #pragma unroll
    for (int i = 0; i < 13; i++) acc[i] = 0ULL;

    const float* actb = g_act + (size_t)b*COMPn*HW;

    for (int cc = 0; cc < COMPn; cc += 8) {
        __syncthreads();
        for (int idx = tid; idx < 8*324; idx += 256) {
            int cl = idx / 324, r = idx - cl*324;
            int ly = r / 18, lx = r - ly*18;
            int gy = row0 - 1 + ly, gx = col0 - 1 + lx;
            float v = 0.f;
            if ((unsigned)gy < Hf && (unsigned)gx < Wf)
                v = actb[(cc+cl)*HW + gy*Wf + gx];
            *reinterpret_cast<u64t*>(&s_act[idx*2]) = dup2(v);
        }
        __syncthreads();

        #pragma unroll 1
        for (int cl = 0; cl < 8; cl++) {
            const int c = cc + cl;
            u64t a[9];
            #pragma unroll
            for (int jy = 0; jy < 3; jy++)
                #pragma unroll
                for (int jx = 0; jx < 3; jx++)
                    a[jy*3+jx] = *reinterpret_cast<const u64t*>(
                        &s_act[(cl*324 + (trow+jy)*18 + (tcol+jx))*2]);

            const float* wb = s_w + c*9*TPAD;
            #pragma unroll
            for (int j = 0; j < 9; j++) {
                const float* wj = wb + j*TPAD;
                const ulonglong2* w2 = reinterpret_cast<const ulonglong2*>(wj);
                ulonglong2 wA = w2[0], wB = w2[1], wC = w2[2];
                ulonglong2 wD = w2[3], wE = w2[4], wF = w2[5];
                u64t wG = *reinterpret_cast<const u64t*>(wj + 24);
                FMA2(acc[0],  wA.x, a[j], acc[0]);
                FMA2(acc[1],  wA.y, a[j], acc[1]);
                FMA2(acc[2],  wB.x, a[j], acc[2]);
                FMA2(acc[3],  wB.y, a[j], acc[3]);
                FMA2(acc[4],  wC.x, a[j], acc[4]);
                FMA2(acc[5],  wC.y, a[j], acc[5]);
                FMA2(acc[6],  wD.x, a[j], acc[6]);
                FMA2(acc[7],  wD.y, a[j], acc[7]);
                FMA2(acc[8],  wE.x, a[j], acc[8]);
                FMA2(acc[9],  wE.y, a[j], acc[9]);
                FMA2(acc[10], wF.x, a[j], acc[10]);
                FMA2(acc[11], wF.y, a[j], acc[11]);
                FMA2(acc[12], wG,   a[j], acc[12]);
            }
        }
    }

    // softmax over t = 0..24
    float v[26];
    #pragma unroll
    for (int i = 0; i < 13; i++) {
        float2 u = unpk(acc[i]);
        v[2*i] = u.x; v[2*i+1] = u.y;
    }
    float mx = v[0];
    #pragma unroll
    for (int t = 1; t < 25; t++) mx = fmaxf(mx, v[t]);
    float sum = 0.f;
    #pragma unroll
    for (int t = 0; t < 25; t++) { v[t] = __expf(v[t] - mx); sum += v[t]; }
    float r = 1.f / sum;

    const int pix = (row0 + trow)*Wf + col0 + tcol;
    float* mp = g_mask + (size_t)(b*HW + pix)*MSTR + q;
    #pragma unroll
    for (int t = 0; t < 25; t++) mp[t*4] = v[t] * r;
}

// ---------------------------------------------------------------------------
// K3: reassembly + pixel shuffle. Mask m-order -> LDG.128 gives packed
// (s0,s1)|(s2,s3) pairs. x patch staged DUPLICATED (LDS.64 -> dup pair,
// no movs in inner loop). Double-buffered. grid (8,8,Bn*2) x 128 thr.
// ---------------------------------------------------------------------------
__global__ __launch_bounds__(128) void k3_reassemble(
    const float* __restrict__ x, float* __restrict__ out)
{
    __shared__ __align__(16) float s_x[2][1152];   // [buf][4ch][12*12][2] dup

    const int tid  = threadIdx.x;
    const int px   = tid & 63;
    const int slot = tid >> 6;
    const int trow = px >> 3, tcol = px & 7;
    const int bz   = blockIdx.z;
    const int b    = bz >> 1;
    const int cbase = (bz & 1) * 128;
    const int col0 = blockIdx.x * 8, row0 = blockIdx.y * 8;
    const int gi = row0 + trow, gj = col0 + tcol;
    const int pix = gi*Wf + gj;

    // masks: 25 LDG.128 -> 50 packed regs
    u64t m01[25], m23[25];
    {
        const ulonglong2* mp = reinterpret_cast<const ulonglong2*>(
            g_mask + (size_t)(b*HW + pix)*MSTR);
        #pragma unroll
        for (int k = 0; k < 25; k++) {
            ulonglong2 mm = mp[k];
            m01[k] = mm.x; m23[k] = mm.y;
        }
    }

    const float* xb   = x   + (size_t)b*Cn*HW;
    float*       outb = out + (size_t)b*Cn*OH*OW;

    float pre[5];
    {
        #pragma unroll
        for (int i = 0; i < 5; i++) {
            int idx = tid + i*128;
            float vv = 0.f;
            if (idx < 576) {
                int cl = idx / 144, rr = idx - cl*144;
                int ly = rr / 12, lx = rr - ly*12;
                int gy = row0 - 2 + ly, gx = col0 - 2 + lx;
                if ((unsigned)gy < Hf && (unsigned)gx < Wf)
                    vv = xb[(cbase + cl)*HW + gy*Wf + gx];
            }
            pre[i] = vv;
        }
        #pragma unroll
        for (int i = 0; i < 5; i++) {
            int idx = tid + i*128;
            if (idx < 576) *reinterpret_cast<u64t*>(&s_x[0][idx*2]) = dup2(pre[i]);
        }
        __syncthreads();
    }

    #pragma unroll 1
    for (int it = 0; it < 32; it++) {
        const int cur = it & 1;
        if (it < 31) {
            #pragma unroll
            for (int i = 0; i < 5; i++) {
                int idx = tid + i*128;
                float vv = 0.f;
                if (idx < 576) {
                    int cl = idx / 144, rr = idx - cl*144;
                    int ly = rr / 12, lx = rr - ly*12;
                    int gy = row0 - 2 + ly, gx = col0 - 2 + lx;
                    if ((unsigned)gy < Hf && (unsigned)gx < Wf)
                        vv = xb[(cbase + (it+1)*4 + cl)*HW + gy*Wf + gx];
                }
                pre[i] = vv;
            }
        }

        const float* p0 = &s_x[cur][((slot*2)*144 + trow*12 + tcol)*2];
        const float* p1 = p0 + 288;
        u64t a01_0 = 0ULL, a23_0 = 0ULL, a01_1 = 0ULL, a23_1 = 0ULL;
        #pragma unroll
        for (int k = 0; k < 25; k++) {
            const int dy = k / 5, dx = k - dy*5;
            const int off = (dy*12 + dx)*2;
            u64t xx0 = *reinterpret_cast<const u64t*>(p0 + off);
            u64t xx1 = *reinterpret_cast<const u64t*>(p1 + off);
            FMA2(a01_0, m01[k], xx0, a01_0);
            FMA2(a23_0, m23[k], xx0, a23_0);
            FMA2(a01_1, m01[k], xx1, a01_1);
            FMA2(a23_1, m23[k], xx1, a23_1);
        }

        const int c0 = cbase + it*4 + slot*2;
        float* op0 = outb + (size_t)c0*OH*OW;
        *reinterpret_cast<float2*>(op0 + (2*gi    )*OW + 2*gj) = unpk(a01_0);
        *reinterpret_cast<float2*>(op0 + (2*gi + 1)*OW + 2*gj) = unpk(a23_0);
        float* op1 = op0 + OH*OW;
        *reinterpret_cast<float2*>(op1 + (2*gi    )*OW + 2*gj) = unpk(a01_1);
        *reinterpret_cast<float2*>(op1 + (2*gi + 1)*OW + 2*gj) = unpk(a23_1);

        if (it < 31) {
            #pragma unroll
            for (int i = 0; i < 5; i++) {
                int idx = tid + i*128;
                if (idx < 576) *reinterpret_cast<u64t*>(&s_x[cur ^ 1][idx*2]) = dup2(pre[i]);
            }
        }
        __syncthreads();
    }
}

// ---------------------------------------------------------------------------
extern "C" void kernel_launch(void* const* d_in, const int* in_sizes, int n_in,
                              void* d_out, int out_size)
{
    const float* x      = (const float*)d_in[0];
    const float* w_comp = (const float*)d_in[1];
    const float* gamma  = (const float*)d_in[2];
    const float* beta   = (const float*)d_in[3];
    const float* mean   = (const float*)d_in[4];
    const float* var    = (const float*)d_in[5];
    const float* w_enc  = (const float*)d_in[6];
    float* out = (float*)d_out;

    const int k2_smem = (64*9*TPAD + 8*324*2) * (int)sizeof(float);  // ~84KB
    static int configured = 0;
    if (!configured) {
        cudaFuncSetAttribute(k2_conv_softmax,
                             cudaFuncAttributeMaxDynamicSharedMemorySize, k2_smem);
        configured = 1;
    }

    k1_comp_bn_silu<<<dim3(Bn*16, 8), 128>>>(x, w_comp, gamma, beta, mean, var);
    k2_conv_softmax<<<dim3(4, 4, Bn*4), 256, k2_smem>>>(w_enc);
    k3_reassemble<<<dim3(8, 8, Bn*2), 128>>>(x, out);
}

// round 4
// speedup vs baseline: 1.5133x; 1.0860x over previous
#include <cuda_runtime.h>

#define Bn   4
#define Cn   256
#define Hf   64
#define Wf   64
#define HW   (Hf*Wf)
#define COMPn 64
#define OH   128
#define OW   128
#define EPSc 1e-5f
#define TPAD 28
#define MSTR 112

typedef unsigned long long u64t;

#define FMA2(d, a, b, c) asm("fma.rn.f32x2 %0, %1, %2, %3;" : "=l"(d) : "l"(a), "l"(b), "l"(c))

__device__ __forceinline__ u64t dup2(float v) {
    u64t r; asm("mov.b64 %0, {%1, %1};" : "=l"(r) : "f"(v)); return r;
}
__device__ __forceinline__ float2 unpk(u64t v) {
    float lo, hi; asm("mov.b64 {%0, %1}, %2;" : "=f"(lo), "=f"(hi) : "l"(v));
    return make_float2(lo, hi);
}

__device__ float g_act[Bn*COMPn*HW];
__device__ float g_mask[Bn*HW*MSTR];

// ---------------------------------------------------------------------------
// K1: 1x1 compression + BN + SiLU. 4-stage software-pipelined x loads.
// grid (64, 8) x 128 thr. 8 outputs x 2 pixels per thread, FFMA2 throughout.
// ---------------------------------------------------------------------------
__global__ __launch_bounds__(128) void k1_comp_bn_silu(
    const float* __restrict__ x, const float* __restrict__ w_comp,
    const float* __restrict__ gamma, const float* __restrict__ beta,
    const float* __restrict__ mean, const float* __restrict__ var)
{
    __shared__ __align__(16) float sw[8*256*2];

    const int tid     = threadIdx.x;
    const int b       = blockIdx.x >> 4;
    const int pixBase = (blockIdx.x & 15) << 8;
    const int oBase   = blockIdx.y << 3;

    for (int i = tid; i < 8*256; i += 128) {
        int o = i >> 8, c = i & 255;
        float w = w_comp[(oBase + o)*256 + c];
        sw[2*i] = w; sw[2*i+1] = w;
    }
    __syncthreads();

    const int pix0 = pixBase + 2*tid;
    const float* xb = x + (size_t)b*Cn*HW + pix0;

    u64t acc[8];
    #pragma unroll
    for (int o = 0; o < 8; o++) acc[o] = 0ULL;

    const ulonglong2* sw2 = reinterpret_cast<const ulonglong2*>(sw);

    u64t A[4], B[4], C[4], D[4];
    #define LD4(BUF, g) { const float* _p = xb + (size_t)(g)*4*HW; \
        BUF[0] = *(const u64t*)(_p); BUF[1] = *(const u64t*)(_p + HW); \
        BUF[2] = *(const u64t*)(_p + 2*HW); BUF[3] = *(const u64t*)(_p + 3*HW); }
    #define K1STEP(BUF, g) { \
        _Pragma("unroll") for (int o = 0; o < 8; o++) { \
            ulonglong2 wA = sw2[o*128 + (g)*2]; \
            ulonglong2 wB = sw2[o*128 + (g)*2 + 1]; \
            FMA2(acc[o], wA.x, BUF[0], acc[o]); \
            FMA2(acc[o], wA.y, BUF[1], acc[o]); \
            FMA2(acc[o], wB.x, BUF[2], acc[o]); \
            FMA2(acc[o], wB.y, BUF[3], acc[o]); } }

    LD4(A, 0); LD4(B, 1); LD4(C, 2); LD4(D, 3);

    #pragma unroll 1
    for (int g = 0; g < 64; g += 4) {
        K1STEP(A, g);     if (g + 4 < 64) LD4(A, g + 4);
        K1STEP(B, g + 1); if (g + 5 < 64) LD4(B, g + 5);
        K1STEP(C, g + 2); if (g + 6 < 64) LD4(C, g + 6);
        K1STEP(D, g + 3); if (g + 7 < 64) LD4(D, g + 7);
    }
    #undef LD4
    #undef K1STEP

    #pragma unroll
    for (int o = 0; o < 8; o++) {
        int og = oBase + o;
        float inv = gamma[og] * rsqrtf(var[og] + EPSc);
        float mu = mean[og], bt = beta[og];
        float2 v = unpk(acc[o]);
        float v0 = (v.x - mu)*inv + bt;
        float v1 = (v.y - mu)*inv + bt;
        v0 = v0 / (1.f + __expf(-v0));
        v1 = v1 / (1.f + __expf(-v1));
        *reinterpret_cast<float2*>(&g_act[((size_t)b*COMPn + og)*HW + pix0]) = make_float2(v0, v1);
    }
}

// ---------------------------------------------------------------------------
// K2: 3x3 encoder conv + softmax. Double-buffered act staging, 1 sync/chunk,
// LDG prefetch overlapped with compute. Weights staged once (63KB).
// grid (4,4,16) x 256 thr, dyn smem ~104KB (2 CTAs/SM).
// ---------------------------------------------------------------------------
#define K2_BUF (8*324*2)   // floats per act buffer

__global__ __launch_bounds__(256) void k2_conv_softmax(const float* __restrict__ w_enc)
{
    extern __shared__ __align__(16) float smem[];
    float* s_w   = smem;                 // [c][j][TPAD] = 16128 floats
    float* s_act = smem + 64*9*TPAD;     // 2 x K2_BUF

    const int tid  = threadIdx.x;
    const int bz   = blockIdx.z;
    const int b    = bz >> 2;
    const int q    = bz & 3;
    const int row0 = blockIdx.y * 16, col0 = blockIdx.x * 16;
    const int trow = tid >> 4, tcol = tid & 15;

    for (int i = tid; i < 576; i += 256) {
        s_w[i*TPAD + 25] = 0.f; s_w[i*TPAD + 26] = 0.f; s_w[i*TPAD + 27] = 0.f;
    }
    for (int idx = tid; idx < 25*576; idx += 256) {
        int t = idx / 576, cj = idx - t*576;
        s_w[cj*TPAD + t] = w_enc[(t*4 + q)*576 + cj];
    }

    const float* actb = g_act + (size_t)b*COMPn*HW;

    float pre[11];
    #define K2_LDG(chunk) { \
        _Pragma("unroll") for (int i = 0; i < 11; i++) { \
            int idx = tid + i*256; float vv = 0.f; \
            if (idx < 2592) { \
                int cl = idx / 324, r = idx - cl*324; \
                int ly = r / 18, lx = r - ly*18; \
                int gy = row0 - 1 + ly, gx = col0 - 1 + lx; \
                if ((unsigned)gy < Hf && (unsigned)gx < Wf) \
                    vv = actb[((chunk)*8 + cl)*HW + gy*Wf + gx]; \
            } \
            pre[i] = vv; } }
    #define K2_STS(buf) { \
        float* _d = s_act + (buf)*K2_BUF; \
        _Pragma("unroll") for (int i = 0; i < 11; i++) { \
            int idx = tid + i*256; \
            if (idx < 2592) *reinterpret_cast<u64t*>(&_d[idx*2]) = dup2(pre[i]); } }

    K2_LDG(0);
    K2_STS(0);
    __syncthreads();

    u64t acc[13];
    #pragma unroll
    for (int i = 0; i < 13; i++) acc[i] = 0ULL;

    #pragma unroll 1
    for (int ch = 0; ch < 8; ch++) {
        if (ch < 7) K2_LDG(ch + 1);

        const float* abuf = s_act + (ch & 1)*K2_BUF;
        #pragma unroll 1
        for (int cl = 0; cl < 8; cl++) {
            const int c = ch*8 + cl;
            u64t a[9];
            #pragma unroll
            for (int jy = 0; jy < 3; jy++)
                #pragma unroll
                for (int jx = 0; jx < 3; jx++)
                    a[jy*3+jx] = *reinterpret_cast<const u64t*>(
                        &abuf[(cl*324 + (trow+jy)*18 + (tcol+jx))*2]);

            const float* wb = s_w + c*9*TPAD;
            #pragma unroll
            for (int j = 0; j < 9; j++) {
                const float* wj = wb + j*TPAD;
                const ulonglong2* w2 = reinterpret_cast<const ulonglong2*>(wj);
                ulonglong2 wA = w2[0], wB = w2[1], wC = w2[2];
                ulonglong2 wD = w2[3], wE = w2[4], wF = w2[5];
                u64t wG = *reinterpret_cast<const u64t*>(wj + 24);
                FMA2(acc[0],  wA.x, a[j], acc[0]);
                FMA2(acc[1],  wA.y, a[j], acc[1]);
                FMA2(acc[2],  wB.x, a[j], acc[2]);
                FMA2(acc[3],  wB.y, a[j], acc[3]);
                FMA2(acc[4],  wC.x, a[j], acc[4]);
                FMA2(acc[5],  wC.y, a[j], acc[5]);
                FMA2(acc[6],  wD.x, a[j], acc[6]);
                FMA2(acc[7],  wD.y, a[j], acc[7]);
                FMA2(acc[8],  wE.x, a[j], acc[8]);
                FMA2(acc[9],  wE.y, a[j], acc[9]);
                FMA2(acc[10], wF.x, a[j], acc[10]);
                FMA2(acc[11], wF.y, a[j], acc[11]);
                FMA2(acc[12], wG,   a[j], acc[12]);
            }
        }

        if (ch < 7) K2_STS((ch + 1) & 1);
        __syncthreads();
    }
    #undef K2_LDG
    #undef K2_STS

    float v[26];
    #pragma unroll
    for (int i = 0; i < 13; i++) {
        float2 u = unpk(acc[i]);
        v[2*i] = u.x; v[2*i+1] = u.y;
    }
    float mx = v[0];
    #pragma unroll
    for (int t = 1; t < 25; t++) mx = fmaxf(mx, v[t]);
    float sum = 0.f;
    #pragma unroll
    for (int t = 0; t < 25; t++) { v[t] = __expf(v[t] - mx); sum += v[t]; }
    float r = 1.f / sum;

    const int pix = (row0 + trow)*Wf + col0 + tcol;
    float* mp = g_mask + (size_t)(b*HW + pix)*MSTR + q;
    #pragma unroll
    for (int t = 0; t < 25; t++) mp[t*4] = v[t] * r;
}

// ---------------------------------------------------------------------------
// K3: reassembly + pixel shuffle. Channel split x4 (grid z=16 -> 1024 blocks).
// Mask in 50 packed regs; x staged dup'd, double-buffered, 1 sync/iter.
// ---------------------------------------------------------------------------
__global__ __launch_bounds__(128) void k3_reassemble(
    const float* __restrict__ x, float* __restrict__ out)
{
    __shared__ __align__(16) float s_x[2][1152];

    const int tid  = threadIdx.x;
    const int px   = tid & 63;
    const int slot = tid >> 6;
    const int trow = px >> 3, tcol = px & 7;
    const int bz   = blockIdx.z;
    const int b    = bz >> 2;
    const int cbase = (bz & 3) * 64;
    const int col0 = blockIdx.x * 8, row0 = blockIdx.y * 8;
    const int gi = row0 + trow, gj = col0 + tcol;
    const int pix = gi*Wf + gj;

    u64t m01[25], m23[25];
    {
        const ulonglong2* mp = reinterpret_cast<const ulonglong2*>(
            g_mask + (size_t)(b*HW + pix)*MSTR);
        #pragma unroll
        for (int k = 0; k < 25; k++) {
            ulonglong2 mm = mp[k];
            m01[k] = mm.x; m23[k] = mm.y;
        }
    }

    const float* xb   = x   + (size_t)b*Cn*HW;
    float*       outb = out + (size_t)b*Cn*OH*OW;

    float pre[5];
    #define K3_LDG(it) { \
        _Pragma("unroll") for (int i = 0; i < 5; i++) { \
            int idx = tid + i*128; float vv = 0.f; \
            if (idx < 576) { \
                int cl = idx / 144, rr = idx - cl*144; \
                int ly = rr / 12, lx = rr - ly*12; \
                int gy = row0 - 2 + ly, gx = col0 - 2 + lx; \
                if ((unsigned)gy < Hf && (unsigned)gx < Wf) \
                    vv = xb[(cbase + (it)*4 + cl)*HW + gy*Wf + gx]; \
            } \
            pre[i] = vv; } }
    #define K3_STS(buf) { \
        _Pragma("unroll") for (int i = 0; i < 5; i++) { \
            int idx = tid + i*128; \
            if (idx < 576) *reinterpret_cast<u64t*>(&s_x[buf][idx*2]) = dup2(pre[i]); } }

    K3_LDG(0);
    K3_STS(0);
    __syncthreads();

    #pragma unroll 1
    for (int it = 0; it < 16; it++) {
        const int cur = it & 1;
        if (it < 15) K3_LDG(it + 1);

        const float* p0 = &s_x[cur][((slot*2)*144 + trow*12 + tcol)*2];
        const float* p1 = p0 + 288;
        u64t a01_0 = 0ULL, a23_0 = 0ULL, a01_1 = 0ULL, a23_1 = 0ULL;
        #pragma unroll
        for (int k = 0; k < 25; k++) {
            const int dy = k / 5, dx = k - dy*5;
            const int off = (dy*12 + dx)*2;
            u64t xx0 = *reinterpret_cast<const u64t*>(p0 + off);
            u64t xx1 = *reinterpret_cast<const u64t*>(p1 + off);
            FMA2(a01_0, m01[k], xx0, a01_0);
            FMA2(a23_0, m23[k], xx0, a23_0);
            FMA2(a01_1, m01[k], xx1, a01_1);
            FMA2(a23_1, m23[k], xx1, a23_1);
        }

        const int c0 = cbase + it*4 + slot*2;
        float* op0 = outb + (size_t)c0*OH*OW;
        *reinterpret_cast<float2*>(op0 + (2*gi    )*OW + 2*gj) = unpk(a01_0);
        *reinterpret_cast<float2*>(op0 + (2*gi + 1)*OW + 2*gj) = unpk(a23_0);
        float* op1 = op0 + OH*OW;
        *reinterpret_cast<float2*>(op1 + (2*gi    )*OW + 2*gj) = unpk(a01_1);
        *reinterpret_cast<float2*>(op1 + (2*gi + 1)*OW + 2*gj) = unpk(a23_1);

        if (it < 15) K3_STS(cur ^ 1);
        __syncthreads();
    }
    #undef K3_LDG
    #undef K3_STS
}

// ---------------------------------------------------------------------------
extern "C" void kernel_launch(void* const* d_in, const int* in_sizes, int n_in,
                              void* d_out, int out_size)
{
    const float* x      = (const float*)d_in[0];
    const float* w_comp = (const float*)d_in[1];
    const float* gamma  = (const float*)d_in[2];
    const float* beta   = (const float*)d_in[3];
    const float* mean   = (const float*)d_in[4];
    const float* var    = (const float*)d_in[5];
    const float* w_enc  = (const float*)d_in[6];
    float* out = (float*)d_out;

    const int k2_smem = (64*9*TPAD + 2*K2_BUF) * (int)sizeof(float);  // ~104KB
    cudaFuncSetAttribute(k2_conv_softmax,
                         cudaFuncAttributeMaxDynamicSharedMemorySize, k2_smem);

    k1_comp_bn_silu<<<dim3(Bn*16, 8), 128>>>(x, w_comp, gamma, beta, mean, var);
    k2_conv_softmax<<<dim3(4, 4, Bn*4), 256, k2_smem>>>(w_enc);
    k3_reassemble<<<dim3(8, 8, Bn*4), 128>>>(x, out);
}

// round 5
// speedup vs baseline: 1.6941x; 1.1195x over previous
#include <cuda_runtime.h>

#define Bn   4
#define Cn   256
#define Hf   64
#define Wf   64
#define HW   (Hf*Wf)
#define COMPn 64
#define OH   128
#define OW   128
#define EPSc 1e-5f
#define TPAD 28
#define MSTR 112       // mask floats per pixel (gmem, packed)
#define MPADS 116      // mask floats per pixel in smem (conflict pad)

typedef unsigned long long u64t;

#define FMA2(d, a, b, c) asm("fma.rn.f32x2 %0, %1, %2, %3;" : "=l"(d) : "l"(a), "l"(b), "l"(c))

__device__ __forceinline__ u64t dup2(float v) {
    u64t r; asm("mov.b64 %0, {%1, %1};" : "=l"(r) : "f"(v)); return r;
}
__device__ __forceinline__ float2 unpk(u64t v) {
    float lo, hi; asm("mov.b64 {%0, %1}, %2;" : "=f"(lo), "=f"(hi) : "l"(v));
    return make_float2(lo, hi);
}

__device__ float g_act[Bn*COMPn*HW];
// masks tile-major: [b][tileY*8+tileX][pixInTile(64)][112], m = t*4 + s
__device__ float g_mask2[Bn*64*64*MSTR];

// ---------------------------------------------------------------------------
// K1: 1x1 compression + BN + SiLU. 8-stage software-pipelined x loads,
// FFMA2 over pixel pairs, dup'd weights in smem (uniform/broadcast LDS.128).
// grid (64, 8) x 128 thr.
// ---------------------------------------------------------------------------
__global__ __launch_bounds__(128) void k1_comp_bn_silu(
    const float* __restrict__ x, const float* __restrict__ w_comp,
    const float* __restrict__ gamma, const float* __restrict__ beta,
    const float* __restrict__ mean, const float* __restrict__ var)
{
    __shared__ __align__(16) float sw[8*256*2];

    const int tid     = threadIdx.x;
    const int b       = blockIdx.x >> 4;
    const int pixBase = (blockIdx.x & 15) << 8;
    const int oBase   = blockIdx.y << 3;

    for (int i = tid; i < 8*256; i += 128) {
        int o = i >> 8, c = i & 255;
        float w = w_comp[(oBase + o)*256 + c];
        sw[2*i] = w; sw[2*i+1] = w;
    }
    __syncthreads();

    const int pix0 = pixBase + 2*tid;
    const float* xb = x + (size_t)b*Cn*HW + pix0;

    u64t acc[8];
    #pragma unroll
    for (int o = 0; o < 8; o++) acc[o] = 0ULL;

    const ulonglong2* sw2 = reinterpret_cast<const ulonglong2*>(sw);

    u64t buf[8][4];
    #define LD4(s, g) { const float* _p = xb + (size_t)(g)*4*HW; \
        buf[s][0] = *(const u64t*)(_p);        buf[s][1] = *(const u64t*)(_p + HW); \
        buf[s][2] = *(const u64t*)(_p + 2*HW); buf[s][3] = *(const u64t*)(_p + 3*HW); }
    #define K1STEP(s, g) { \
        _Pragma("unroll") for (int o = 0; o < 8; o++) { \
            ulonglong2 wA = sw2[o*128 + (g)*2]; \
            ulonglong2 wB = sw2[o*128 + (g)*2 + 1]; \
            FMA2(acc[o], wA.x, buf[s][0], acc[o]); \
            FMA2(acc[o], wA.y, buf[s][1], acc[o]); \
            FMA2(acc[o], wB.x, buf[s][2], acc[o]); \
            FMA2(acc[o], wB.y, buf[s][3], acc[o]); } }

    #pragma unroll
    for (int s = 0; s < 8; s++) LD4(s, s);

    #pragma unroll 1
    for (int g = 0; g < 56; g += 8) {
        #pragma unroll
        for (int s = 0; s < 8; s++) {
            K1STEP(s, g + s);
            LD4(s, g + 8 + s);
        }
    }
    #pragma unroll
    for (int s = 0; s < 8; s++) K1STEP(s, 56 + s);
    #undef LD4
    #undef K1STEP

    #pragma unroll
    for (int o = 0; o < 8; o++) {
        int og = oBase + o;
        float inv = gamma[og] * rsqrtf(var[og] + EPSc);
        float mu = mean[og], bt = beta[og];
        float2 v = unpk(acc[o]);
        float v0 = (v.x - mu)*inv + bt;
        float v1 = (v.y - mu)*inv + bt;
        v0 = v0 / (1.f + __expf(-v0));
        v1 = v1 / (1.f + __expf(-v1));
        *reinterpret_cast<float2*>(&g_act[((size_t)b*COMPn + og)*HW + pix0]) = make_float2(v0, v1);
    }
}

// ---------------------------------------------------------------------------
// K2: 3x3 encoder conv + softmax. Acts stored PLAIN in smem (LDS.32, row pad
// 18->19, dup in register). Weights staged once, t-padded, uniform LDS.
// Double-buffered acts, 1 sync/chunk. grid (4,4,16) x 256 thr, smem ~86KB.
// ---------------------------------------------------------------------------
#define K2_BUF (8*342)   // 8 ch x 18 rows x 19 cols (plain floats)

__global__ __launch_bounds__(256) void k2_conv_softmax(const float* __restrict__ w_enc)
{
    extern __shared__ __align__(16) float smem[];
    float* s_w   = smem;                 // [c][j][TPAD] = 16128 floats
    float* s_act = smem + 64*9*TPAD;     // 2 x K2_BUF

    const int tid  = threadIdx.x;
    const int bz   = blockIdx.z;
    const int b    = bz >> 2;
    const int q    = bz & 3;
    const int row0 = blockIdx.y * 16, col0 = blockIdx.x * 16;
    const int trow = tid >> 4, tcol = tid & 15;

    for (int i = tid; i < 576; i += 256) {
        s_w[i*TPAD + 25] = 0.f; s_w[i*TPAD + 26] = 0.f; s_w[i*TPAD + 27] = 0.f;
    }
    for (int idx = tid; idx < 25*576; idx += 256) {
        int t = idx / 576, cj = idx - t*576;
        s_w[cj*TPAD + t] = w_enc[(t*4 + q)*576 + cj];
    }

    const float* actb = g_act + (size_t)b*COMPn*HW;

    float pre[11];
    #define K2_LDG(chunk) { \
        _Pragma("unroll") for (int i = 0; i < 11; i++) { \
            int idx = tid + i*256; float vv = 0.f; \
            if (idx < 2592) { \
                int cl = idx / 324, r = idx - cl*324; \
                int ly = r / 18, lx = r - ly*18; \
                int gy = row0 - 1 + ly, gx = col0 - 1 + lx; \
                if ((unsigned)gy < Hf && (unsigned)gx < Wf) \
                    vv = actb[((chunk)*8 + cl)*HW + gy*Wf + gx]; \
            } \
            pre[i] = vv; } }
    #define K2_STS(buf) { \
        float* _d = s_act + (buf)*K2_BUF; \
        _Pragma("unroll") for (int i = 0; i < 11; i++) { \
            int idx = tid + i*256; \
            if (idx < 2592) { \
                int cl = idx / 324, r = idx - cl*324; \
                int ly = r / 18, lx = r - ly*18; \
                _d[cl*342 + ly*19 + lx] = pre[i]; } } }

    K2_LDG(0);
    K2_STS(0);
    __syncthreads();

    u64t acc[13];
    #pragma unroll
    for (int i = 0; i < 13; i++) acc[i] = 0ULL;

    #pragma unroll 1
    for (int ch = 0; ch < 8; ch++) {
        if (ch < 7) K2_LDG(ch + 1);

        const float* abuf = s_act + (ch & 1)*K2_BUF;
        #pragma unroll 1
        for (int cl = 0; cl < 8; cl++) {
            const int c = ch*8 + cl;
            u64t a[9];
            #pragma unroll
            for (int jy = 0; jy < 3; jy++)
                #pragma unroll
                for (int jx = 0; jx < 3; jx++)
                    a[jy*3+jx] = dup2(abuf[cl*342 + (trow+jy)*19 + (tcol+jx)]);

            const float* wb = s_w + c*9*TPAD;
            #pragma unroll
            for (int j = 0; j < 9; j++) {
                const float* wj = wb + j*TPAD;
                const ulonglong2* w2 = reinterpret_cast<const ulonglong2*>(wj);
                ulonglong2 wA = w2[0], wB = w2[1], wC = w2[2];
                ulonglong2 wD = w2[3], wE = w2[4], wF = w2[5];
                u64t wG = *reinterpret_cast<const u64t*>(wj + 24);
                FMA2(acc[0],  wA.x, a[j], acc[0]);
                FMA2(acc[1],  wA.y, a[j], acc[1]);
                FMA2(acc[2],  wB.x, a[j], acc[2]);
                FMA2(acc[3],  wB.y, a[j], acc[3]);
                FMA2(acc[4],  wC.x, a[j], acc[4]);
                FMA2(acc[5],  wC.y, a[j], acc[5]);
                FMA2(acc[6],  wD.x, a[j], acc[6]);
                FMA2(acc[7],  wD.y, a[j], acc[7]);
                FMA2(acc[8],  wE.x, a[j], acc[8]);
                FMA2(acc[9],  wE.y, a[j], acc[9]);
                FMA2(acc[10], wF.x, a[j], acc[10]);
                FMA2(acc[11], wF.y, a[j], acc[11]);
                FMA2(acc[12], wG,   a[j], acc[12]);
            }
        }

        if (ch < 7) K2_STS((ch + 1) & 1);
        __syncthreads();
    }
    #undef K2_LDG
    #undef K2_STS

    float v[26];
    #pragma unroll
    for (int i = 0; i < 13; i++) {
        float2 u = unpk(acc[i]);
        v[2*i] = u.x; v[2*i+1] = u.y;
    }
    float mx = v[0];
    #pragma unroll
    for (int t = 1; t < 25; t++) mx = fmaxf(mx, v[t]);
    float sum = 0.f;
    #pragma unroll
    for (int t = 0; t < 25; t++) { v[t] = __expf(v[t] - mx); sum += v[t]; }
    float r = 1.f / sum;

    const int gi = row0 + trow, gj = col0 + tcol;
    const int tY = gi >> 3, tX = gj >> 3;
    const int pit = ((gi & 7) << 3) | (gj & 7);
    float* mp = g_mask2 + ((size_t)((b*64 + tY*8 + tX)*64 + pit))*MSTR + q;
    #pragma unroll
    for (int t = 0; t < 25; t++) mp[t*4] = v[t] * r;
}

// ---------------------------------------------------------------------------
// K3: reassembly + pixel shuffle. Masks staged via COALESCED LDG.128 ->
// padded smem -> 50 packed regs. x staged plain (LDS.32 + reg dup, row pad
// 12->13). Double-buffered, 1 sync/iter. grid (8,8,16) x 128 thr.
// ---------------------------------------------------------------------------
#define XSTR 156   // 12 rows x 13 padded cols per channel

__global__ __launch_bounds__(128) void k3_reassemble(
    const float* __restrict__ x, float* __restrict__ out)
{
    __shared__ __align__(16) float s_mask[64*MPADS];   // 29.7KB
    __shared__ __align__(16) float s_x[2][4*XSTR];     // 5KB

    const int tid  = threadIdx.x;
    const int px   = tid & 63;
    const int slot = tid >> 6;
    const int trow = px >> 3, tcol = px & 7;
    const int bz   = blockIdx.z;
    const int b    = bz >> 2;
    const int cbase = (bz & 3) * 64;
    const int col0 = blockIdx.x * 8, row0 = blockIdx.y * 8;
    const int gi = row0 + trow, gj = col0 + tcol;

    // --- stage masks coalesced: 64 px x 112 floats = 1792 float4 ---
    {
        const float4* gm = reinterpret_cast<const float4*>(
            g_mask2 + (size_t)((b*64 + blockIdx.y*8 + blockIdx.x)*64)*MSTR);
        #pragma unroll
        for (int j = 0; j < 14; j++) {
            int i4 = tid + j*128;
            float4 v = gm[i4];
            int f = i4*4;
            int pxi = f / MSTR, off = f - pxi*MSTR;
            *reinterpret_cast<float4*>(&s_mask[pxi*MPADS + off]) = v;
        }
    }

    const float* xb   = x   + (size_t)b*Cn*HW;
    float*       outb = out + (size_t)b*Cn*OH*OW;

    float pre[5];
    #define K3_LDG(it) { \
        _Pragma("unroll") for (int i = 0; i < 5; i++) { \
            int idx = tid + i*128; float vv = 0.f; \
            if (idx < 576) { \
                int cl = idx / 144, rr = idx - cl*144; \
                int ly = rr / 12, lx = rr - ly*12; \
                int gy = row0 - 2 + ly, gx = col0 - 2 + lx; \
                if ((unsigned)gy < Hf && (unsigned)gx < Wf) \
                    vv = xb[(cbase + (it)*4 + cl)*HW + gy*Wf + gx]; \
            } \
            pre[i] = vv; } }
    #define K3_STS(buf) { \
        _Pragma("unroll") for (int i = 0; i < 5; i++) { \
            int idx = tid + i*128; \
            if (idx < 576) { \
                int cl = idx / 144, rr = idx - cl*144; \
                int ly = rr / 12, lx = rr - ly*12; \
                s_x[buf][cl*XSTR + ly*13 + lx] = pre[i]; } } }

    K3_LDG(0);
    K3_STS(0);
    __syncthreads();

    // masks -> 50 packed regs
    u64t m01[25], m23[25];
    {
        const ulonglong2* mp = reinterpret_cast<const ulonglong2*>(&s_mask[px*MPADS]);
        #pragma unroll
        for (int k = 0; k < 25; k++) {
            ulonglong2 mm = mp[k];
            m01[k] = mm.x; m23[k] = mm.y;
        }
    }

    #pragma unroll 1
    for (int it = 0; it < 16; it++) {
        const int cur = it & 1;
        if (it < 15) K3_LDG(it + 1);

        const float* p0 = &s_x[cur][(slot*2)*XSTR + trow*13 + tcol];
        u64t a01_0 = 0ULL, a23_0 = 0ULL, a01_1 = 0ULL, a23_1 = 0ULL;
        #pragma unroll
        for (int k = 0; k < 25; k++) {
            const int dy = k / 5, dx = k - dy*5;
            const int off = dy*13 + dx;
            u64t xx0 = dup2(p0[off]);
            u64t xx1 = dup2(p0[off + XSTR]);
            FMA2(a01_0, m01[k], xx0, a01_0);
            FMA2(a23_0, m23[k], xx0, a23_0);
            FMA2(a01_1, m01[k], xx1, a01_1);
            FMA2(a23_1, m23[k], xx1, a23_1);
        }

        const int c0 = cbase + it*4 + slot*2;
        float* op0 = outb + (size_t)c0*OH*OW;
        *reinterpret_cast<float2*>(op0 + (2*gi    )*OW + 2*gj) = unpk(a01_0);
        *reinterpret_cast<float2*>(op0 + (2*gi + 1)*OW + 2*gj) = unpk(a23_0);
        float* op1 = op0 + OH*OW;
        *reinterpret_cast<float2*>(op1 + (2*gi    )*OW + 2*gj) = unpk(a01_1);
        *reinterpret_cast<float2*>(op1 + (2*gi + 1)*OW + 2*gj) = unpk(a23_1);

        if (it < 15) K3_STS(cur ^ 1);
        __syncthreads();
    }
    #undef K3_LDG
    #undef K3_STS
}

// ---------------------------------------------------------------------------
extern "C" void kernel_launch(void* const* d_in, const int* in_sizes, int n_in,
                              void* d_out, int out_size)
{
    const float* x      = (const float*)d_in[0];
    const float* w_comp = (const float*)d_in[1];
    const float* gamma  = (const float*)d_in[2];
    const float* beta   = (const float*)d_in[3];
    const float* mean   = (const float*)d_in[4];
    const float* var    = (const float*)d_in[5];
    const float* w_enc  = (const float*)d_in[6];
    float* out = (float*)d_out;

    const int k2_smem = (64*9*TPAD + 2*K2_BUF) * (int)sizeof(float);  // ~86KB
    cudaFuncSetAttribute(k2_conv_softmax,
                         cudaFuncAttributeMaxDynamicSharedMemorySize, k2_smem);

    k1_comp_bn_silu<<<dim3(Bn*16, 8), 128>>>(x, w_comp, gamma, beta, mean, var);
    k2_conv_softmax<<<dim3(4, 4, Bn*4), 256, k2_smem>>>(w_enc);
    k3_reassemble<<<dim3(8, 8, Bn*4), 128>>>(x, out);
}

// round 6
// speedup vs baseline: 1.7286x; 1.0203x over previous
#include <cuda_runtime.h>

#define Bn   4
#define Cn   256
#define Hf   64
#define Wf   64
#define HW   (Hf*Wf)
#define COMPn 64
#define OH   128
#define OW   128
#define EPSc 1e-5f
#define TPAD 28
#define MSTR 112
#define MPADS 116

typedef unsigned long long u64t;

#define FMA2(d, a, b, c) asm("fma.rn.f32x2 %0, %1, %2, %3;" : "=l"(d) : "l"(a), "l"(b), "l"(c))
#define ADD2(d, a, b)    asm("add.rn.f32x2 %0, %1, %2;"     : "=l"(d) : "l"(a), "l"(b))

__device__ __forceinline__ u64t dup2(float v) {
    u64t r; asm("mov.b64 %0, {%1, %1};" : "=l"(r) : "f"(v)); return r;
}
__device__ __forceinline__ float2 unpk(u64t v) {
    float lo, hi; asm("mov.b64 {%0, %1}, %2;" : "=f"(lo), "=f"(hi) : "l"(v));
    return make_float2(lo, hi);
}

__device__ float g_act[Bn*COMPn*HW];
// masks tile-major: [b][tileY*8+tileX][pixInTile(64)][112], m = t*4 + s
__device__ float g_mask2[Bn*64*64*MSTR];

// ---------------------------------------------------------------------------
// K1: 1x1 compression + BN + SiLU. Block = 256 thr = 2 c-halves x 128 px-thr.
// Each half: 2 px x 8 outputs x 128 channels, double-buffered x loads,
// FFMA2 throughout. Partials reduced via smem; epilogue split 4+4 outputs.
// grid (64, 8) = 512 blocks -> ~28 warps/SM.
// ---------------------------------------------------------------------------
__global__ __launch_bounds__(256) void k1_comp_bn_silu(
    const float* __restrict__ x, const float* __restrict__ w_comp,
    const float* __restrict__ gamma, const float* __restrict__ beta,
    const float* __restrict__ mean, const float* __restrict__ var)
{
    __shared__ __align__(16) float sw[8*256*2];      // 16KB dup pairs
    __shared__ __align__(16) u64t red[128][2][4];    // 8KB

    const int tid     = threadIdx.x;
    const int h       = tid >> 7;
    const int ht      = tid & 127;
    const int b       = blockIdx.x >> 4;
    const int pixBase = (blockIdx.x & 15) << 8;
    const int oBase   = blockIdx.y << 3;

    for (int i = tid; i < 8*256; i += 256) {
        int o = i >> 8, c = i & 255;
        float w = w_comp[(oBase + o)*256 + c];
        sw[2*i] = w; sw[2*i+1] = w;
    }
    __syncthreads();

    const int pix0 = pixBase + 2*ht;
    const float* xb = x + (size_t)b*Cn*HW + (size_t)(h*128)*HW + pix0;

    u64t acc[8];
    #pragma unroll
    for (int o = 0; o < 8; o++) acc[o] = 0ULL;

    const ulonglong2* sw2 = reinterpret_cast<const ulonglong2*>(sw);
    const int c4Base = h*32;

    u64t buf[2][4];
    #define LD4(s, g) { const float* _p = xb + (size_t)(g)*4*HW; \
        buf[s][0] = *(const u64t*)(_p);        buf[s][1] = *(const u64t*)(_p + HW); \
        buf[s][2] = *(const u64t*)(_p + 2*HW); buf[s][3] = *(const u64t*)(_p + 3*HW); }
    #define K1STEP(s, g) { const int _gc = c4Base + (g); \
        _Pragma("unroll") for (int o = 0; o < 8; o++) { \
            ulonglong2 wA = sw2[o*128 + _gc*2]; \
            ulonglong2 wB = sw2[o*128 + _gc*2 + 1]; \
            FMA2(acc[o], wA.x, buf[s][0], acc[o]); \
            FMA2(acc[o], wA.y, buf[s][1], acc[o]); \
            FMA2(acc[o], wB.x, buf[s][2], acc[o]); \
            FMA2(acc[o], wB.y, buf[s][3], acc[o]); } }

    LD4(0, 0); LD4(1, 1);
    #pragma unroll 1
    for (int g = 0; g < 32; g += 2) {
        K1STEP(0, g);     if (g + 2 < 32) LD4(0, g + 2);
        K1STEP(1, g + 1); if (g + 3 < 32) LD4(1, g + 3);
    }
    #undef LD4
    #undef K1STEP

    // exchange foreign 4 outputs, keep own 4
    #pragma unroll
    for (int j = 0; j < 4; j++) red[ht][1 ^ h][j] = acc[(1 ^ h)*4 + j];
    __syncthreads();
    #pragma unroll
    for (int j = 0; j < 4; j++) {
        u64t o = acc[h*4 + j];
        ADD2(o, o, red[ht][h][j]);
        acc[h*4 + j] = o;
    }

    #pragma unroll
    for (int j = 0; j < 4; j++) {
        int og = oBase + h*4 + j;
        float inv = gamma[og] * rsqrtf(var[og] + EPSc);
        float mu = mean[og], bt = beta[og];
        float2 v = unpk(acc[h*4 + j]);
        float v0 = (v.x - mu)*inv + bt;
        float v1 = (v.y - mu)*inv + bt;
        v0 = v0 / (1.f + __expf(-v0));
        v1 = v1 / (1.f + __expf(-v1));
        *reinterpret_cast<float2*>(&g_act[((size_t)b*COMPn + og)*HW + pix0]) = make_float2(v0, v1);
    }
}

// ---------------------------------------------------------------------------
// K2: 3x3 encoder conv + softmax. Block = 256 thr = 2 c-halves x 128 px
// (16x8 tile). Each half does 32 channels; partial accs reduced via smem.
// Weights staged once (63KB, t-padded); acts double-buffered (16ch chunks).
// grid (4,8,16) = 512 blocks -> ~28 warps/SM, smem ~87KB (2 CTAs/SM).
// ---------------------------------------------------------------------------
#define K2PCH 190            // 10 rows x 19 padded cols per channel
#define K2_BUF (16*K2PCH)    // floats per act buffer (16 channels)

__global__ __launch_bounds__(256) void k2_conv_softmax(const float* __restrict__ w_enc)
{
    extern __shared__ __align__(16) float smem[];
    float* s_w   = smem;                 // 64*9*TPAD = 16128 floats
    float* s_act = smem + 64*9*TPAD;     // 2 x K2_BUF = 6080 floats

    const int tid  = threadIdx.x;
    const int h    = tid >> 7;
    const int pxt  = tid & 127;
    const int bz   = blockIdx.z;
    const int b    = bz >> 2;
    const int q    = bz & 3;
    const int row0 = blockIdx.y * 8, col0 = blockIdx.x * 16;
    const int trow = pxt >> 4, tcol = pxt & 15;

    const float* actb = g_act + (size_t)b*COMPn*HW;

    // prefetch act chunk 0 (LDG latency overlaps weight staging below)
    float pre[12];
    #define K2_LDG(chunk) { \
        _Pragma("unroll") for (int i = 0; i < 12; i++) { \
            int idx = tid + i*256; float vv = 0.f; \
            if (idx < 2880) { \
                int cl = idx / 180, r = idx - cl*180; \
                int ly = r / 18, lx = r - ly*18; \
                int gy = row0 - 1 + ly, gx = col0 - 1 + lx; \
                if ((unsigned)gy < Hf && (unsigned)gx < Wf) \
                    vv = actb[((chunk)*16 + cl)*HW + gy*Wf + gx]; \
            } \
            pre[i] = vv; } }
    #define K2_STS(buf) { \
        float* _d = s_act + (buf)*K2_BUF; \
        _Pragma("unroll") for (int i = 0; i < 12; i++) { \
            int idx = tid + i*256; \
            if (idx < 2880) { \
                int cl = idx / 180, r = idx - cl*180; \
                int ly = r / 18, lx = r - ly*18; \
                _d[cl*K2PCH + ly*19 + lx] = pre[i]; } } }

    K2_LDG(0);

    for (int i = tid; i < 576; i += 256) {
        s_w[i*TPAD + 25] = 0.f; s_w[i*TPAD + 26] = 0.f; s_w[i*TPAD + 27] = 0.f;
    }
    for (int idx = tid; idx < 25*576; idx += 256) {
        int t = idx / 576, cj = idx - t*576;
        s_w[cj*TPAD + t] = w_enc[(t*4 + q)*576 + cj];
    }

    K2_STS(0);
    __syncthreads();

    u64t acc[13];
    #pragma unroll
    for (int i = 0; i < 13; i++) acc[i] = 0ULL;

    #pragma unroll 1
    for (int ch = 0; ch < 4; ch++) {
        if (ch < 3) K2_LDG(ch + 1);

        const float* abuf = s_act + (ch & 1)*K2_BUF + (h*8)*K2PCH;
        #pragma unroll 1
        for (int cl = 0; cl < 8; cl++) {
            const int c = ch*16 + h*8 + cl;
            u64t a[9];
            #pragma unroll
            for (int jy = 0; jy < 3; jy++)
                #pragma unroll
                for (int jx = 0; jx < 3; jx++)
                    a[jy*3+jx] = dup2(abuf[cl*K2PCH + (trow+jy)*19 + (tcol+jx)]);

            const float* wb = s_w + c*9*TPAD;
            #pragma unroll
            for (int j = 0; j < 9; j++) {
                const float* wj = wb + j*TPAD;
                const ulonglong2* w2 = reinterpret_cast<const ulonglong2*>(wj);
                ulonglong2 wA = w2[0], wB = w2[1], wC = w2[2];
                ulonglong2 wD = w2[3], wE = w2[4], wF = w2[5];
                u64t wG = *reinterpret_cast<const u64t*>(wj + 24);
                FMA2(acc[0],  wA.x, a[j], acc[0]);
                FMA2(acc[1],  wA.y, a[j], acc[1]);
                FMA2(acc[2],  wB.x, a[j], acc[2]);
                FMA2(acc[3],  wB.y, a[j], acc[3]);
                FMA2(acc[4],  wC.x, a[j], acc[4]);
                FMA2(acc[5],  wC.y, a[j], acc[5]);
                FMA2(acc[6],  wD.x, a[j], acc[6]);
                FMA2(acc[7],  wD.y, a[j], acc[7]);
                FMA2(acc[8],  wE.x, a[j], acc[8]);
                FMA2(acc[9],  wE.y, a[j], acc[9]);
                FMA2(acc[10], wF.x, a[j], acc[10]);
                FMA2(acc[11], wF.y, a[j], acc[11]);
                FMA2(acc[12], wG,   a[j], acc[12]);
            }
        }

        if (ch < 3) K2_STS((ch + 1) & 1);
        __syncthreads();
    }
    #undef K2_LDG
    #undef K2_STS

    // cross-half reduction (reuse act buffer region; safe after final sync)
    u64t* red = reinterpret_cast<u64t*>(s_act);
    if (h == 1) {
        #pragma unroll
        for (int i = 0; i < 13; i++) red[pxt*13 + i] = acc[i];
    }
    __syncthreads();
    if (h == 0) {
        #pragma unroll
        for (int i = 0; i < 13; i++) {
            u64t o = acc[i];
            ADD2(o, o, red[pxt*13 + i]);
            acc[i] = o;
        }

        float v[26];
        #pragma unroll
        for (int i = 0; i < 13; i++) {
            float2 u = unpk(acc[i]);
            v[2*i] = u.x; v[2*i+1] = u.y;
        }
        float mx = v[0];
        #pragma unroll
        for (int t = 1; t < 25; t++) mx = fmaxf(mx, v[t]);
        float sum = 0.f;
        #pragma unroll
        for (int t = 0; t < 25; t++) { v[t] = __expf(v[t] - mx); sum += v[t]; }
        float r = 1.f / sum;

        const int gi = row0 + trow, gj = col0 + tcol;
        const int tY = gi >> 3, tX = gj >> 3;
        const int pit = ((gi & 7) << 3) | (gj & 7);
        float* mp = g_mask2 + ((size_t)((b*64 + tY*8 + tX)*64 + pit))*MSTR + q;
        #pragma unroll
        for (int t = 0; t < 25; t++) mp[t*4] = v[t] * r;
    }
}

// ---------------------------------------------------------------------------
// K3: reassembly + pixel shuffle (unchanged from R5).
// ---------------------------------------------------------------------------
#define XSTR 156

__global__ __launch_bounds__(128) void k3_reassemble(
    const float* __restrict__ x, float* __restrict__ out)
{
    __shared__ __align__(16) float s_mask[64*MPADS];
    __shared__ __align__(16) float s_x[2][4*XSTR];

    const int tid  = threadIdx.x;
    const int px   = tid & 63;
    const int slot = tid >> 6;
    const int trow = px >> 3, tcol = px & 7;
    const int bz   = blockIdx.z;
    const int b    = bz >> 2;
    const int cbase = (bz & 3) * 64;
    const int col0 = blockIdx.x * 8, row0 = blockIdx.y * 8;
    const int gi = row0 + trow, gj = col0 + tcol;

    {
        const float4* gm = reinterpret_cast<const float4*>(
            g_mask2 + (size_t)((b*64 + blockIdx.y*8 + blockIdx.x)*64)*MSTR);
        #pragma unroll
        for (int j = 0; j < 14; j++) {
            int i4 = tid + j*128;
            float4 v = gm[i4];
            int f = i4*4;
            int pxi = f / MSTR, off = f - pxi*MSTR;
            *reinterpret_cast<float4*>(&s_mask[pxi*MPADS + off]) = v;
        }
    }

    const float* xb   = x   + (size_t)b*Cn*HW;
    float*       outb = out + (size_t)b*Cn*OH*OW;

    float pre[5];
    #define K3_LDG(it) { \
        _Pragma("unroll") for (int i = 0; i < 5; i++) { \
            int idx = tid + i*128; float vv = 0.f; \
            if (idx < 576) { \
                int cl = idx / 144, rr = idx - cl*144; \
                int ly = rr / 12, lx = rr - ly*12; \
                int gy = row0 - 2 + ly, gx = col0 - 2 + lx; \
                if ((unsigned)gy < Hf && (unsigned)gx < Wf) \
                    vv = xb[(cbase + (it)*4 + cl)*HW + gy*Wf + gx]; \
            } \
            pre[i] = vv; } }
    #define K3_STS(buf) { \
        _Pragma("unroll") for (int i = 0; i < 5; i++) { \
            int idx = tid + i*128; \
            if (idx < 576) { \
                int cl = idx / 144, rr = idx - cl*144; \
                int ly = rr / 12, lx = rr - ly*12; \
                s_x[buf][cl*XSTR + ly*13 + lx] = pre[i]; } } }

    K3_LDG(0);
    K3_STS(0);
    __syncthreads();

    u64t m01[25], m23[25];
    {
        const ulonglong2* mp = reinterpret_cast<const ulonglong2*>(&s_mask[px*MPADS]);
        #pragma unroll
        for (int k = 0; k < 25; k++) {
            ulonglong2 mm = mp[k];
            m01[k] = mm.x; m23[k] = mm.y;
        }
    }

    #pragma unroll 1
    for (int it = 0; it < 16; it++) {
        const int cur = it & 1;
        if (it < 15) K3_LDG(it + 1);

        const float* p0 = &s_x[cur][(slot*2)*XSTR + trow*13 + tcol];
        u64t a01_0 = 0ULL, a23_0 = 0ULL, a01_1 = 0ULL, a23_1 = 0ULL;
        #pragma unroll
        for (int k = 0; k < 25; k++) {
            const int dy = k / 5, dx = k - dy*5;
            const int off = dy*13 + dx;
            u64t xx0 = dup2(p0[off]);
            u64t xx1 = dup2(p0[off + XSTR]);
            FMA2(a01_0, m01[k], xx0, a01_0);
            FMA2(a23_0, m23[k], xx0, a23_0);
            FMA2(a01_1, m01[k], xx1, a01_1);
            FMA2(a23_1, m23[k], xx1, a23_1);
        }

        const int c0 = cbase + it*4 + slot*2;
        float* op0 = outb + (size_t)c0*OH*OW;
        *reinterpret_cast<float2*>(op0 + (2*gi    )*OW + 2*gj) = unpk(a01_0);
        *reinterpret_cast<float2*>(op0 + (2*gi + 1)*OW + 2*gj) = unpk(a23_0);
        float* op1 = op0 + OH*OW;
        *reinterpret_cast<float2*>(op1 + (2*gi    )*OW + 2*gj) = unpk(a01_1);
        *reinterpret_cast<float2*>(op1 + (2*gi + 1)*OW + 2*gj) = unpk(a23_1);

        if (it < 15) K3_STS(cur ^ 1);
        __syncthreads();
    }
    #undef K3_LDG
    #undef K3_STS
}

// ---------------------------------------------------------------------------
extern "C" void kernel_launch(void* const* d_in, const int* in_sizes, int n_in,
                              void* d_out, int out_size)
{
    const float* x      = (const float*)d_in[0];
    const float* w_comp = (const float*)d_in[1];
    const float* gamma  = (const float*)d_in[2];
    const float* beta   = (const float*)d_in[3];
    const float* mean   = (const float*)d_in[4];
    const float* var    = (const float*)d_in[5];
    const float* w_enc  = (const float*)d_in[6];
    float* out = (float*)d_out;

    const int k2_smem = (64*9*TPAD + 2*K2_BUF) * (int)sizeof(float);  // ~87KB
    cudaFuncSetAttribute(k2_conv_softmax,
                         cudaFuncAttributeMaxDynamicSharedMemorySize, k2_smem);

    k1_comp_bn_silu<<<dim3(Bn*16, 8), 256>>>(x, w_comp, gamma, beta, mean, var);
    k2_conv_softmax<<<dim3(4, 8, Bn*4), 256, k2_smem>>>(w_enc);
    k3_reassemble<<<dim3(8, 8, Bn*4), 128>>>(x, out);
}

// round 7
// speedup vs baseline: 2.0842x; 1.2057x over previous
#include <cuda_runtime.h>

#define Bn   4
#define Cn   256
#define Hf   64
#define Wf   64
#define HW   (Hf*Wf)
#define COMPn 64
#define OH   128
#define OW   128
#define EPSc 1e-5f
#define TPAD 28

typedef unsigned long long u64t;

#define FMA2(d, a, b, c) asm("fma.rn.f32x2 %0, %1, %2, %3;" : "=l"(d) : "l"(a), "l"(b), "l"(c))
#define ADD2(d, a, b)    asm("add.rn.f32x2 %0, %1, %2;"     : "=l"(d) : "l"(a), "l"(b))

__device__ __forceinline__ u64t dup2(float v) {
    u64t r; asm("mov.b64 %0, {%1, %1};" : "=l"(r) : "f"(v)); return r;
}
__device__ __forceinline__ float2 unpk(u64t v) {
    float lo, hi; asm("mov.b64 {%0, %1}, %2;" : "=f"(lo), "=f"(hi) : "l"(v));
    return make_float2(lo, hi);
}
__device__ __forceinline__ u64t pack2(float a, float b) {
    u64t r; asm("mov.b64 %0, {%1, %2};" : "=l"(r) : "f"(a), "f"(b)); return r;
}

__device__ float g_act[Bn*COMPn*HW];
// masks q-major: [b][q][tileY*8+tileX][pixInTile(64)][28], value index = t (0..24)
__device__ float g_mask3[Bn*4*64*64*28];

// ---------------------------------------------------------------------------
// K1: 1x1 compression + BN + SiLU. Block = 256 thr = 2 c-halves x 128 px-thr,
// 4 px/thread (LDG.128), 8 outputs. 16 LDS.128 + 4 LDG.128 per 64 FFMA2.
// grid (32, 8) = 256 blocks.
// ---------------------------------------------------------------------------
__global__ __launch_bounds__(256) void k1_comp_bn_silu(
    const float* __restrict__ x, const float* __restrict__ w_comp,
    const float* __restrict__ gamma, const float* __restrict__ beta,
    const float* __restrict__ mean, const float* __restrict__ var)
{
    __shared__ __align__(16) float sw[8*256*2];        // 16KB dup pairs
    __shared__ __align__(16) u64t red[128][2][4][2];   // 16KB

    const int tid     = threadIdx.x;
    const int h       = tid >> 7;
    const int ht      = tid & 127;
    const int b       = blockIdx.x >> 3;
    const int pixBase = (blockIdx.x & 7) << 9;
    const int oBase   = blockIdx.y << 3;

    for (int i = tid; i < 8*256; i += 256) {
        int o = i >> 8, c = i & 255;
        float w = w_comp[(oBase + o)*256 + c];
        sw[2*i] = w; sw[2*i+1] = w;
    }
    __syncthreads();

    const int pix0 = pixBase + 4*ht;
    const float* xb = x + (size_t)b*Cn*HW + (size_t)(h*128)*HW + pix0;

    u64t acc[8][2];
    #pragma unroll
    for (int o = 0; o < 8; o++) { acc[o][0] = 0ULL; acc[o][1] = 0ULL; }

    const ulonglong2* sw2 = reinterpret_cast<const ulonglong2*>(sw);
    const int c4Base = h*32;

    ulonglong2 buf[2][4];
    #define LD4(s, g) { const float* _p = xb + (size_t)(g)*4*HW; \
        buf[s][0] = *(const ulonglong2*)(_p); \
        buf[s][1] = *(const ulonglong2*)(_p + HW); \
        buf[s][2] = *(const ulonglong2*)(_p + 2*HW); \
        buf[s][3] = *(const ulonglong2*)(_p + 3*HW); }
    #define K1STEP(s, g) { const int _gc = c4Base + (g); \
        _Pragma("unroll") for (int o = 0; o < 8; o++) { \
            ulonglong2 wA = sw2[o*128 + _gc*2]; \
            ulonglong2 wB = sw2[o*128 + _gc*2 + 1]; \
            FMA2(acc[o][0], wA.x, buf[s][0].x, acc[o][0]); \
            FMA2(acc[o][1], wA.x, buf[s][0].y, acc[o][1]); \
            FMA2(acc[o][0], wA.y, buf[s][1].x, acc[o][0]); \
            FMA2(acc[o][1], wA.y, buf[s][1].y, acc[o][1]); \
            FMA2(acc[o][0], wB.x, buf[s][2].x, acc[o][0]); \
            FMA2(acc[o][1], wB.x, buf[s][2].y, acc[o][1]); \
            FMA2(acc[o][0], wB.y, buf[s][3].x, acc[o][0]); \
            FMA2(acc[o][1], wB.y, buf[s][3].y, acc[o][1]); } }

    LD4(0, 0); LD4(1, 1);
    #pragma unroll 1
    for (int g = 0; g < 32; g += 2) {
        K1STEP(0, g);     if (g + 2 < 32) LD4(0, g + 2);
        K1STEP(1, g + 1); if (g + 3 < 32) LD4(1, g + 3);
    }
    #undef LD4
    #undef K1STEP

    // exchange foreign 4 outputs
    #pragma unroll
    for (int j = 0; j < 4; j++) {
        red[ht][1 ^ h][j][0] = acc[(1 ^ h)*4 + j][0];
        red[ht][1 ^ h][j][1] = acc[(1 ^ h)*4 + j][1];
    }
    __syncthreads();

    #pragma unroll
    for (int j = 0; j < 4; j++) {
        int og = oBase + h*4 + j;
        u64t a0 = acc[h*4 + j][0], a1 = acc[h*4 + j][1];
        ADD2(a0, a0, red[ht][h][j][0]);
        ADD2(a1, a1, red[ht][h][j][1]);
        float inv = gamma[og] * rsqrtf(var[og] + EPSc);
        float mu = mean[og], bt = beta[og];
        float2 p0 = unpk(a0), p1 = unpk(a1);
        float v0 = (p0.x - mu)*inv + bt;
        float v1 = (p0.y - mu)*inv + bt;
        float v2 = (p1.x - mu)*inv + bt;
        float v3 = (p1.y - mu)*inv + bt;
        v0 = v0 / (1.f + __expf(-v0));
        v1 = v1 / (1.f + __expf(-v1));
        v2 = v2 / (1.f + __expf(-v2));
        v3 = v3 / (1.f + __expf(-v3));
        *reinterpret_cast<float4*>(&g_act[((size_t)b*COMPn + og)*HW + pix0]) =
            make_float4(v0, v1, v2, v3);
    }
}

// ---------------------------------------------------------------------------
// K2: 3x3 encoder conv + softmax. Block = 128 thr, 2 horiz px/thread
// (16x16 tile). Weight LDS amortized over 2 px: 7 LDS per 26 FFMA2 per j.
// Acts double-buffered in 4-ch chunks. Masks stored q-major, STG.128.
// grid (4,4,16) = 256 blocks, smem ~74KB.
// ---------------------------------------------------------------------------
#define K2PCH 342            // 18 rows x 19 padded cols
#define K2_BUF (4*K2PCH)

__global__ __launch_bounds__(128) void k2_conv_softmax(const float* __restrict__ w_enc)
{
    extern __shared__ __align__(16) float smem[];
    float* s_w   = smem;                 // 64*9*TPAD = 16128 floats
    float* s_act = smem + 64*9*TPAD;     // 2 x K2_BUF = 2736 floats

    const int tid   = threadIdx.x;
    const int trow  = tid >> 3;
    const int tcol0 = (tid & 7) << 1;
    const int bz    = blockIdx.z;
    const int b     = bz >> 2;
    const int q     = bz & 3;
    const int row0  = blockIdx.y * 16, col0 = blockIdx.x * 16;

    const float* actb = g_act + (size_t)b*COMPn*HW;

    float pre[11];
    #define K2_LDG(chunk) { \
        _Pragma("unroll") for (int i = 0; i < 11; i++) { \
            int idx = tid + i*128; float vv = 0.f; \
            if (idx < 1296) { \
                int cl = idx / 324, r = idx - cl*324; \
                int ly = r / 18, lx = r - ly*18; \
                int gy = row0 - 1 + ly, gx = col0 - 1 + lx; \
                if ((unsigned)gy < Hf && (unsigned)gx < Wf) \
                    vv = actb[((chunk)*4 + cl)*HW + gy*Wf + gx]; \
            } \
            pre[i] = vv; } }
    #define K2_STS(buf) { \
        float* _d = s_act + (buf)*K2_BUF; \
        _Pragma("unroll") for (int i = 0; i < 11; i++) { \
            int idx = tid + i*128; \
            if (idx < 1296) { \
                int cl = idx / 324, r = idx - cl*324; \
                int ly = r / 18, lx = r - ly*18; \
                _d[cl*K2PCH + ly*19 + lx] = pre[i]; } } }

    K2_LDG(0);

    for (int i = tid; i < 576; i += 128) {
        s_w[i*TPAD + 25] = 0.f; s_w[i*TPAD + 26] = 0.f; s_w[i*TPAD + 27] = 0.f;
    }
    for (int idx = tid; idx < 25*576; idx += 128) {
        int t = idx / 576, cj = idx - t*576;
        s_w[cj*TPAD + t] = w_enc[(t*4 + q)*576 + cj];
    }

    K2_STS(0);
    __syncthreads();

    u64t acc[2][13];
    #pragma unroll
    for (int p = 0; p < 2; p++)
        #pragma unroll
        for (int i = 0; i < 13; i++) acc[p][i] = 0ULL;

    #pragma unroll 1
    for (int ch = 0; ch < 16; ch++) {
        if (ch < 15) K2_LDG(ch + 1);

        const float* abuf = s_act + (ch & 1)*K2_BUF;
        #pragma unroll 1
        for (int cl = 0; cl < 4; cl++) {
            const int c = ch*4 + cl;
            const float* ab = abuf + cl*K2PCH + trow*19 + tcol0;
            u64t ad[3][4];
            #pragma unroll
            for (int jy = 0; jy < 3; jy++)
                #pragma unroll
                for (int jx = 0; jx < 4; jx++)
                    ad[jy][jx] = dup2(ab[jy*19 + jx]);

            const float* wb = s_w + c*9*TPAD;
            #pragma unroll
            for (int jy = 0; jy < 3; jy++)
            #pragma unroll
            for (int jx = 0; jx < 3; jx++) {
                const float* wj = wb + (jy*3 + jx)*TPAD;
                const ulonglong2* w2 = reinterpret_cast<const ulonglong2*>(wj);
                ulonglong2 wA = w2[0], wB = w2[1], wC = w2[2];
                ulonglong2 wD = w2[3], wE = w2[4], wF = w2[5];
                u64t wG = *reinterpret_cast<const u64t*>(wj + 24);
                u64t a0 = ad[jy][jx], a1 = ad[jy][jx+1];
                FMA2(acc[0][0],  wA.x, a0, acc[0][0]);  FMA2(acc[1][0],  wA.x, a1, acc[1][0]);
                FMA2(acc[0][1],  wA.y, a0, acc[0][1]);  FMA2(acc[1][1],  wA.y, a1, acc[1][1]);
                FMA2(acc[0][2],  wB.x, a0, acc[0][2]);  FMA2(acc[1][2],  wB.x, a1, acc[1][2]);
                FMA2(acc[0][3],  wB.y, a0, acc[0][3]);  FMA2(acc[1][3],  wB.y, a1, acc[1][3]);
                FMA2(acc[0][4],  wC.x, a0, acc[0][4]);  FMA2(acc[1][4],  wC.x, a1, acc[1][4]);
                FMA2(acc[0][5],  wC.y, a0, acc[0][5]);  FMA2(acc[1][5],  wC.y, a1, acc[1][5]);
                FMA2(acc[0][6],  wD.x, a0, acc[0][6]);  FMA2(acc[1][6],  wD.x, a1, acc[1][6]);
                FMA2(acc[0][7],  wD.y, a0, acc[0][7]);  FMA2(acc[1][7],  wD.y, a1, acc[1][7]);
                FMA2(acc[0][8],  wE.x, a0, acc[0][8]);  FMA2(acc[1][8],  wE.x, a1, acc[1][8]);
                FMA2(acc[0][9],  wE.y, a0, acc[0][9]);  FMA2(acc[1][9],  wE.y, a1, acc[1][9]);
                FMA2(acc[0][10], wF.x, a0, acc[0][10]); FMA2(acc[1][10], wF.x, a1, acc[1][10]);
                FMA2(acc[0][11], wF.y, a0, acc[0][11]); FMA2(acc[1][11], wF.y, a1, acc[1][11]);
                FMA2(acc[0][12], wG,   a0, acc[0][12]); FMA2(acc[1][12], wG,   a1, acc[1][12]);
            }
        }

        if (ch < 15) K2_STS((ch + 1) & 1);
        __syncthreads();
    }
    #undef K2_LDG
    #undef K2_STS

    // softmax over t, store q-major with STG.128
    const int gi = row0 + trow;
    #pragma unroll
    for (int p = 0; p < 2; p++) {
        float v[28];
        #pragma unroll
        for (int i = 0; i < 13; i++) {
            float2 u = unpk(acc[p][i]);
            v[2*i] = u.x; v[2*i+1] = u.y;
        }
        float mx = v[0];
        #pragma unroll
        for (int t = 1; t < 25; t++) mx = fmaxf(mx, v[t]);
        float sum = 0.f;
        #pragma unroll
        for (int t = 0; t < 25; t++) { v[t] = __expf(v[t] - mx); sum += v[t]; }
        float r = 1.f / sum;
        #pragma unroll
        for (int t = 0; t < 25; t++) v[t] *= r;
        v[25] = 0.f; v[26] = 0.f; v[27] = 0.f;

        const int gj = col0 + tcol0 + p;
        const int tY = gi >> 3, tX = gj >> 3;
        const int pit = ((gi & 7) << 3) | (gj & 7);
        float* mp = g_mask3 + ((size_t)(((b*4 + q)*64 + tY*8 + tX)*64 + pit))*28;
        #pragma unroll
        for (int i = 0; i < 7; i++)
            *reinterpret_cast<float4*>(mp + 4*i) =
                make_float4(v[4*i], v[4*i+1], v[4*i+2], v[4*i+3]);
    }
}

// ---------------------------------------------------------------------------
// K3: reassembly + pixel shuffle. q-major masks staged coalesced, packed
// into 50 u64 regs per thread once. x plain smem + reg dup, double-buffered.
// grid (8,8,16) x 128 thr.
// ---------------------------------------------------------------------------
#define XSTR 156   // 12 x 13 pad
#define MP3 116    // per-px smem stride ([q][29] sub-layout)

__global__ __launch_bounds__(128) void k3_reassemble(
    const float* __restrict__ x, float* __restrict__ out)
{
    __shared__ __align__(16) float s_mask[64*MP3];   // 29.7KB
    __shared__ __align__(16) float s_x[2][4*XSTR];   // 5KB

    const int tid  = threadIdx.x;
    const int px   = tid & 63;
    const int slot = tid >> 6;
    const int trow = px >> 3, tcol = px & 7;
    const int bz   = blockIdx.z;
    const int b    = bz >> 2;
    const int cbase = (bz & 3) * 64;
    const int col0 = blockIdx.x * 8, row0 = blockIdx.y * 8;
    const int gi = row0 + trow, gj = col0 + tcol;
    const int tileIdx = blockIdx.y*8 + blockIdx.x;

    // stage masks: 4 q-planes, each 64px x 28 floats contiguous
    #pragma unroll
    for (int qq = 0; qq < 4; qq++) {
        const float4* gm = reinterpret_cast<const float4*>(
            g_mask3 + (size_t)(((b*4 + qq)*64 + tileIdx)*64)*28);
        #pragma unroll
        for (int j = 0; j < 4; j++) {
            int i4 = tid + j*128;
            if (i4 < 448) {
                float4 v = gm[i4];
                int f = i4*4;
                int pxi = f / 28, t = f - pxi*28;
                float* d = &s_mask[pxi*MP3 + qq*29 + t];
                d[0] = v.x; d[1] = v.y; d[2] = v.z; d[3] = v.w;
            }
        }
    }

    const float* xb   = x   + (size_t)b*Cn*HW;
    float*       outb = out + (size_t)b*Cn*OH*OW;

    float pre[5];
    #define K3_LDG(it) { \
        _Pragma("unroll") for (int i = 0; i < 5; i++) { \
            int idx = tid + i*128; float vv = 0.f; \
            if (idx < 576) { \
                int cl = idx / 144, rr = idx - cl*144; \
                int ly = rr / 12, lx = rr - ly*12; \
                int gy = row0 - 2 + ly, gx = col0 - 2 + lx; \
                if ((unsigned)gy < Hf && (unsigned)gx < Wf) \
                    vv = xb[(cbase + (it)*4 + cl)*HW + gy*Wf + gx]; \
            } \
            pre[i] = vv; } }
    #define K3_STS(buf) { \
        _Pragma("unroll") for (int i = 0; i < 5; i++) { \
            int idx = tid + i*128; \
            if (idx < 576) { \
                int cl = idx / 144, rr = idx - cl*144; \
                int ly = rr / 12, lx = rr - ly*12; \
                s_x[buf][cl*XSTR + ly*13 + lx] = pre[i]; } } }

    K3_LDG(0);
    K3_STS(0);
    __syncthreads();

    // pack masks: m01[k]=(q0,q1), m23[k]=(q2,q3)
    u64t m01[25], m23[25];
    {
        const float* sm = &s_mask[px*MP3];
        #pragma unroll
        for (int k = 0; k < 25; k++) {
            m01[k] = pack2(sm[k],      sm[29 + k]);
            m23[k] = pack2(sm[58 + k], sm[87 + k]);
        }
    }

    #pragma unroll 1
    for (int it = 0; it < 16; it++) {
        const int cur = it & 1;
        if (it < 15) K3_LDG(it + 1);

        const float* p0 = &s_x[cur][(slot*2)*XSTR + trow*13 + tcol];
        u64t a01_0 = 0ULL, a23_0 = 0ULL, a01_1 = 0ULL, a23_1 = 0ULL;
        #pragma unroll
        for (int k = 0; k < 25; k++) {
            const int dy = k / 5, dx = k - dy*5;
            const int off = dy*13 + dx;
            u64t xx0 = dup2(p0[off]);
            u64t xx1 = dup2(p0[off + XSTR]);
            FMA2(a01_0, m01[k], xx0, a01_0);
            FMA2(a23_0, m23[k], xx0, a23_0);
            FMA2(a01_1, m01[k], xx1, a01_1);
            FMA2(a23_1, m23[k], xx1, a23_1);
        }

        const int c0 = cbase + it*4 + slot*2;
        float* op0 = outb + (size_t)c0*OH*OW;
        *reinterpret_cast<float2*>(op0 + (2*gi    )*OW + 2*gj) = unpk(a01_0);
        *reinterpret_cast<float2*>(op0 + (2*gi + 1)*OW + 2*gj) = unpk(a23_0);
        float* op1 = op0 + OH*OW;
        *reinterpret_cast<float2*>(op1 + (2*gi    )*OW + 2*gj) = unpk(a01_1);
        *reinterpret_cast<float2*>(op1 + (2*gi + 1)*OW + 2*gj) = unpk(a23_1);

        if (it < 15) K3_STS(cur ^ 1);
        __syncthreads();
    }
    #undef K3_LDG
    #undef K3_STS
}

// ---------------------------------------------------------------------------
extern "C" void kernel_launch(void* const* d_in, const int* in_sizes, int n_in,
                              void* d_out, int out_size)
{
    const float* x      = (const float*)d_in[0];
    const float* w_comp = (const float*)d_in[1];
    const float* gamma  = (const float*)d_in[2];
    const float* beta   = (const float*)d_in[3];
    const float* mean   = (const float*)d_in[4];
    const float* var    = (const float*)d_in[5];
    const float* w_enc  = (const float*)d_in[6];
    float* out = (float*)d_out;

    const int k2_smem = (64*9*TPAD + 2*K2_BUF) * (int)sizeof(float);  // ~74KB
    cudaFuncSetAttribute(k2_conv_softmax,
                         cudaFuncAttributeMaxDynamicSharedMemorySize, k2_smem);

    k1_comp_bn_silu<<<dim3(Bn*8, 8), 256>>>(x, w_comp, gamma, beta, mean, var);
    k2_conv_softmax<<<dim3(4, 4, Bn*4), 128, k2_smem>>>(w_enc);
    k3_reassemble<<<dim3(8, 8, Bn*4), 128>>>(x, out);
}